// round 12
// baseline (speedup 1.0000x reference)
#include <cuda_runtime.h>
#include <math.h>
#include <stdint.h>

#define BB 131072
#define HD 1024

// ---------------- scratch (device globals; no allocation) ----------------
__device__ float g_h2[(size_t)BB * HD];   // 512MB: h2
__device__ float g_h3[(size_t)BB * HD];   // 512MB: h3
__device__ float g_act[(size_t)BB * HD];  // 512MB: layer-1 activations
__device__ float g_w2t[HD * HD];          // tf32-rounded W2
__device__ float g_w3t[HD * HD];          // tf32-rounded W3
__device__ float g_ps[1024 * HD];         // partial column sums
__device__ float g_pq[1024 * HD];         // partial column sumsq
__device__ float g_scale[HD];
__device__ float g_shift[HD];

// ---------------- helpers ----------------
__device__ __forceinline__ unsigned tf32_bits(float x) {
    unsigned u;
    asm("cvt.rna.tf32.f32 %0, %1;" : "=r"(u) : "f"(x));
    return u;
}

// ---------------- layer1 stats: partial sums of x@W1+b1 (no h store) ------
__global__ void k_layer1_stats(const float* __restrict__ x,
                               const float* __restrict__ W1,
                               const float* __restrict__ b1,
                               float* __restrict__ ps, float* __restrict__ pq) {
    __shared__ float xs[256 * 3];
    const int blk = blockIdx.x;
    const int tid = threadIdx.x;
    const int row0 = blk * 256;
    for (int i = tid; i < 768; i += 256) xs[i] = x[(size_t)row0 * 3 + i];
    __syncthreads();

    const int c = tid * 4;
    float w0[4], w1[4], w2[4], bb[4];
#pragma unroll
    for (int e = 0; e < 4; e++) {
        w0[e] = W1[c + e];
        w1[e] = W1[HD + c + e];
        w2[e] = W1[2 * HD + c + e];
        bb[e] = b1[c + e];
    }
    float s[4] = {0.f, 0.f, 0.f, 0.f}, q[4] = {0.f, 0.f, 0.f, 0.f};
    for (int r = 0; r < 256; r++) {
        float x0 = xs[3 * r], x1 = xs[3 * r + 1], x2 = xs[3 * r + 2];
#pragma unroll
        for (int e = 0; e < 4; e++) {
            float t = fmaf(x0, w0[e], bb[e]);
            t = fmaf(x1, w1[e], t);
            t = fmaf(x2, w2[e], t);
            s[e] += t;
            q[e] = fmaf(t, t, q[e]);
        }
    }
#pragma unroll
    for (int e = 0; e < 4; e++) {
        ps[(size_t)blk * HD + c + e] = s[e];
        pq[(size_t)blk * HD + c + e] = q[e];
    }
}

// ---------------- layer1 act: recompute h1 from x, BN+ReLU+tf32 -> act ----
__global__ void k_act1(const float* __restrict__ x, const float* __restrict__ W1,
                       const float* __restrict__ b1, const float* __restrict__ scale,
                       const float* __restrict__ shift, float* __restrict__ act) {
    __shared__ float xs[256 * 3];
    const int blk = blockIdx.x;
    const int tid = threadIdx.x;
    const int row0 = blk * 256;
    for (int i = tid; i < 768; i += 256) xs[i] = x[(size_t)row0 * 3 + i];
    __syncthreads();

    const int c = tid * 4;
    float w0[4], w1[4], w2[4], bb[4], sc[4], sh[4];
#pragma unroll
    for (int e = 0; e < 4; e++) {
        w0[e] = W1[c + e];
        w1[e] = W1[HD + c + e];
        w2[e] = W1[2 * HD + c + e];
        bb[e] = b1[c + e];
        sc[e] = scale[c + e];
        sh[e] = shift[c + e];
    }
    for (int r = 0; r < 256; r++) {
        float x0 = xs[3 * r], x1 = xs[3 * r + 1], x2 = xs[3 * r + 2];
        float v[4];
#pragma unroll
        for (int e = 0; e < 4; e++) {
            float t = fmaf(x0, w0[e], bb[e]);
            t = fmaf(x1, w1[e], t);
            t = fmaf(x2, w2[e], t);
            v[e] = __uint_as_float(tf32_bits(fmaxf(fmaf(t, sc[e], sh[e]), 0.f)));
        }
        *(float4*)(act + (size_t)(row0 + r) * HD + c) =
            make_float4(v[0], v[1], v[2], v[3]);
    }
}

// ---------------- reduce partials -> per-column scale/shift (1 blk/col) ---
__global__ void k_reduce2(const float* __restrict__ ps, const float* __restrict__ pq,
                          const float* __restrict__ g, const float* __restrict__ bt,
                          float* __restrict__ scale, float* __restrict__ shift,
                          int parts) {
    const int c = blockIdx.x;
    const int tid = threadIdx.x;
    float s = 0.f, q = 0.f;
    for (int p = tid; p < parts; p += 256) {
        s += ps[(size_t)p * HD + c];
        q += pq[(size_t)p * HD + c];
    }
    __shared__ float ss[8], qq[8];
#pragma unroll
    for (int o = 16; o; o >>= 1) {
        s += __shfl_xor_sync(0xffffffffu, s, o);
        q += __shfl_xor_sync(0xffffffffu, q, o);
    }
    if ((tid & 31) == 0) { ss[tid >> 5] = s; qq[tid >> 5] = q; }
    __syncthreads();
    if (tid == 0) {
        float S = 0.f, Q = 0.f;
#pragma unroll
        for (int w = 0; w < 8; w++) { S += ss[w]; Q += qq[w]; }
        const float invB = 1.0f / (float)BB;
        float mu = S * invB;
        float var = fmaxf(Q * invB - mu * mu, 0.f);
        float sc = g[c] * rsqrtf(var + 1e-5f);
        scale[c] = sc;
        shift[c] = bt[c] - mu * sc;
    }
}

// ---------------- weight round to tf32 ------------------------------------
__global__ void k_cvtw(const float* __restrict__ w, float* __restrict__ o) {
    const size_t i = (size_t)blockIdx.x * 256 + threadIdx.x;  // one float4
    float4 v = ((const float4*)w)[i];
    float4 r;
    r.x = __uint_as_float(tf32_bits(v.x));
    r.y = __uint_as_float(tf32_bits(v.y));
    r.z = __uint_as_float(tf32_bits(v.z));
    r.w = __uint_as_float(tf32_bits(v.w));
    ((float4*)o)[i] = r;
}

// ---------------- TF32 GEMM: C[BBxHD] = ACT(A)[BBxHD] @ W[HDxHD] + bias ---
// CTA tile 128x128x32, 8 warps (2x4), m16n8k8 tf32 mma.sync, cp.async 2-stage
// (identical mainloop to the 3812us passing version). FUSE: A holds raw
// pre-BN values; BN+ReLU+tf32 applied at fragment load (bit-identical to the
// standalone activation pass). Fused per-column sum/sumsq partials.
#define ASTR 36
#define BSTR 136
#define ASZ (128 * ASTR)  // 4608 floats
#define BSZ (32 * BSTR)   // 4352 floats
#define GEMM_SMEM_BYTES (2 * (ASZ + BSZ) * 4)  // 71680

template <bool FUSE>
__global__ void __launch_bounds__(256, 2)
k_gemm(const float* __restrict__ A, const float* __restrict__ Bw,
       const float* __restrict__ bias, const float* __restrict__ scA,
       const float* __restrict__ shA, float* __restrict__ C,
       float* __restrict__ ps, float* __restrict__ pq) {
    extern __shared__ float sm[];
    __shared__ float sred[8][32], qred[8][32];
    const int tid = threadIdx.x;
    const int m0 = blockIdx.y * 128;
    const int n0 = blockIdx.x * 128;

    const unsigned smA = (unsigned)__cvta_generic_to_shared(sm);
    const unsigned smB = smA + 2u * ASZ * 4u;

    const int ar = tid >> 3, aq = tid & 7;
    const int br = tid >> 5, bq = tid & 31;

    const float* Ag = A + (size_t)(m0 + ar) * HD + aq * 4;
    const float* Bg = Bw + (size_t)br * HD + n0 + bq * 4;
    const unsigned aS = (unsigned)(ar * ASTR + aq * 4) * 4u;
    const unsigned bS = (unsigned)(br * BSTR + bq * 4) * 4u;

    auto load_tile = [&](int stage, int k0) {
        unsigned a_s = smA + (unsigned)stage * (ASZ * 4u) + aS;
        const float* a_g = Ag + k0;
#pragma unroll
        for (int j = 0; j < 4; j++) {
            asm volatile("cp.async.cg.shared.global [%0], [%1], 16;" ::"r"(
                             a_s + (unsigned)(j * 32 * ASTR * 4)),
                         "l"(a_g + (size_t)32 * HD * j));
        }
        unsigned b_s = smB + (unsigned)stage * (BSZ * 4u) + bS;
        const float* b_g = Bg + (size_t)k0 * HD;
#pragma unroll
        for (int j = 0; j < 4; j++) {
            asm volatile("cp.async.cg.shared.global [%0], [%1], 16;" ::"r"(
                             b_s + (unsigned)(j * 8 * BSTR * 4)),
                         "l"(b_g + (size_t)8 * HD * j));
        }
        asm volatile("cp.async.commit_group;");
    };

    float acc[4][4][4];
#pragma unroll
    for (int a = 0; a < 4; a++)
#pragma unroll
        for (int b = 0; b < 4; b++)
#pragma unroll
            for (int c = 0; c < 4; c++) acc[a][b][c] = 0.f;

    const int lane = tid & 31, ly = lane >> 2, lx = lane & 3;
    const int wid = tid >> 5;
    const int wm = (wid & 1) * 64;
    const int wn = (tid >> 6) * 32;

    load_tile(0, 0);
#pragma unroll 1
    for (int t = 0; t < 32; t++) {
        if (t < 31) {
            load_tile((t + 1) & 1, (t + 1) * 32);
            asm volatile("cp.async.wait_group 1;");
        } else {
            asm volatile("cp.async.wait_group 0;");
        }
        __syncthreads();
        const float* As = sm + (t & 1) * ASZ;
        const float* Bs = sm + 2 * ASZ + (t & 1) * BSZ;
#pragma unroll
        for (int kk = 0; kk < 32; kk += 8) {
            unsigned af[4][4], bf[4][2];
            float sc0, sh0, sc1, sh1;
            if (FUSE) {
                const int kg = t * 32 + kk + lx;
                sc0 = __ldg(scA + kg);     sh0 = __ldg(shA + kg);
                sc1 = __ldg(scA + kg + 4); sh1 = __ldg(shA + kg + 4);
            }
#pragma unroll
            for (int mi = 0; mi < 4; mi++) {
                const float* p = As + (wm + mi * 16 + ly) * ASTR + kk + lx;
                if (FUSE) {
                    af[mi][0] = tf32_bits(fmaxf(fmaf(p[0],            sc0, sh0), 0.f));
                    af[mi][1] = tf32_bits(fmaxf(fmaf(p[8 * ASTR],     sc0, sh0), 0.f));
                    af[mi][2] = tf32_bits(fmaxf(fmaf(p[4],            sc1, sh1), 0.f));
                    af[mi][3] = tf32_bits(fmaxf(fmaf(p[8 * ASTR + 4], sc1, sh1), 0.f));
                } else {
                    af[mi][0] = __float_as_uint(p[0]);
                    af[mi][1] = __float_as_uint(p[8 * ASTR]);
                    af[mi][2] = __float_as_uint(p[4]);
                    af[mi][3] = __float_as_uint(p[8 * ASTR + 4]);
                }
            }
#pragma unroll
            for (int ni = 0; ni < 4; ni++) {
                const float* p = Bs + (kk + lx) * BSTR + wn + ni * 8 + ly;
                bf[ni][0] = __float_as_uint(p[0]);
                bf[ni][1] = __float_as_uint(p[4 * BSTR]);
            }
#pragma unroll
            for (int mi = 0; mi < 4; mi++)
#pragma unroll
                for (int ni = 0; ni < 4; ni++) {
                    asm volatile(
                        "mma.sync.aligned.m16n8k8.row.col.f32.tf32.tf32.f32 "
                        "{%0,%1,%2,%3}, {%4,%5,%6,%7}, {%8,%9}, {%0,%1,%2,%3};"
                        : "+f"(acc[mi][ni][0]), "+f"(acc[mi][ni][1]),
                          "+f"(acc[mi][ni][2]), "+f"(acc[mi][ni][3])
                        : "r"(af[mi][0]), "r"(af[mi][1]), "r"(af[mi][2]), "r"(af[mi][3]),
                          "r"(bf[ni][0]), "r"(bf[ni][1]));
                }
        }
        __syncthreads();
    }

    // Epilogue: store C = acc + bias, and accumulate per-column s/q partials.
    float sc_[4][2] = {{0.f, 0.f}, {0.f, 0.f}, {0.f, 0.f}, {0.f, 0.f}};
    float qc_[4][2] = {{0.f, 0.f}, {0.f, 0.f}, {0.f, 0.f}, {0.f, 0.f}};
#pragma unroll
    for (int mi = 0; mi < 4; mi++) {
        const int r0 = m0 + wm + mi * 16 + ly;
#pragma unroll
        for (int ni = 0; ni < 4; ni++) {
            const int c = n0 + wn + ni * 8 + 2 * lx;
            const float bc0 = bias[c], bc1 = bias[c + 1];
            float2 v0 = make_float2(acc[mi][ni][0] + bc0, acc[mi][ni][1] + bc1);
            float2 v1 = make_float2(acc[mi][ni][2] + bc0, acc[mi][ni][3] + bc1);
            *(float2*)(C + (size_t)r0 * HD + c) = v0;
            *(float2*)(C + (size_t)(r0 + 8) * HD + c) = v1;
            sc_[ni][0] += v0.x + v1.x;
            sc_[ni][1] += v0.y + v1.y;
            qc_[ni][0] = fmaf(v0.x, v0.x, fmaf(v1.x, v1.x, qc_[ni][0]));
            qc_[ni][1] = fmaf(v0.y, v0.y, fmaf(v1.y, v1.y, qc_[ni][1]));
        }
    }
#pragma unroll
    for (int ni = 0; ni < 4; ni++) {
#pragma unroll
        for (int j = 0; j < 2; j++) {
            float s = sc_[ni][j], q = qc_[ni][j];
#pragma unroll
            for (int o = 4; o <= 16; o <<= 1) {
                s += __shfl_xor_sync(0xffffffffu, s, o);
                q += __shfl_xor_sync(0xffffffffu, q, o);
            }
            if (lane < 4) {
                sred[wid][ni * 8 + 2 * lx + j] = s;
                qred[wid][ni * 8 + 2 * lx + j] = q;
            }
        }
    }
    __syncthreads();
    if (tid < 128) {
        const int col = tid;
        const int gpair = (col >> 5) * 2;
        const int cc = col & 31;
        ps[(size_t)blockIdx.y * HD + n0 + col] = sred[gpair][cc] + sred[gpair + 1][cc];
        pq[(size_t)blockIdx.y * HD + n0 + col] = qred[gpair][cc] + qred[gpair + 1][cc];
    }
}

// ---------------- final: thetas = relu(bn(h3)) @ W4 + b4; kinematics ------
__device__ __forceinline__ void dh_mat(float M[3][4], float th, float r, float ca,
                                       float sa) {
    float ct = cosf(th), st = sinf(th);
    M[0][0] = ct;  M[0][1] = -st * ca; M[0][2] = st * sa;  M[0][3] = r * ct;
    M[1][0] = st;  M[1][1] = ct * ca;  M[1][2] = -ct * sa; M[1][3] = r * st;
    M[2][0] = 0.f; M[2][1] = sa;       M[2][2] = ca;       M[2][3] = 0.f;
}

__device__ __forceinline__ void matmul34(const float A[3][4], const float Bm[3][4],
                                         float C[3][4]) {
#pragma unroll
    for (int i = 0; i < 3; i++) {
#pragma unroll
        for (int j = 0; j < 4; j++) {
            float v = A[i][0] * Bm[0][j] + A[i][1] * Bm[1][j] + A[i][2] * Bm[2][j];
            if (j == 3) v += A[i][3];
            C[i][j] = v;
        }
    }
}

__global__ void k_final(const float* __restrict__ h3, const float* __restrict__ scale,
                        const float* __restrict__ shift, const float* __restrict__ W4,
                        const float* __restrict__ b4, float* __restrict__ out) {
    __shared__ float w4s[3072];
    __shared__ float b4s[3];
    const int tid = threadIdx.x;
    for (int i = tid; i < 3072; i += 256) w4s[i] = W4[i];
    if (tid < 3) b4s[tid] = b4[tid];
    __syncthreads();

    const int lane = tid & 31;
    const size_t row = (size_t)blockIdx.x * 8 + (tid >> 5);
    const float* hr = h3 + row * HD;
    float t0 = 0.f, t1 = 0.f, t2 = 0.f;
    for (int k = lane; k < HD; k += 32) {
        float a = fmaxf(fmaf(hr[k], scale[k], shift[k]), 0.f);
        t0 = fmaf(a, w4s[3 * k + 0], t0);
        t1 = fmaf(a, w4s[3 * k + 1], t1);
        t2 = fmaf(a, w4s[3 * k + 2], t2);
    }
#pragma unroll
    for (int o = 16; o > 0; o >>= 1) {
        t0 += __shfl_xor_sync(0xffffffffu, t0, o);
        t1 += __shfl_xor_sync(0xffffffffu, t1, o);
        t2 += __shfl_xor_sync(0xffffffffu, t2, o);
    }
    if (lane == 0) {
        const float th0 = t0 + b4s[0];
        const float th1 = t1 + b4s[1];
        const float th2 = t2 + b4s[2];
        out[row * 3 + 0] = th0;
        out[row * 3 + 1] = th1;
        out[row * 3 + 2] = th2;

        const float PI2 = 1.57079632679489661923f;
        float M[3][4], Nn[3][4], P[3][4];
        dh_mat(M, th0, 0.f, cosf(PI2), sinf(PI2));
        dh_mat(Nn, th1, 0.12f, 1.f, 0.f);
        matmul34(M, Nn, P);
        dh_mat(Nn, th2, 0.115f, 1.f, 0.f);
        matmul34(P, Nn, M);
        float* op = out + (size_t)BB * 3 + row * 3;
        op[0] = M[0][3];
        op[1] = M[1][3];
        op[2] = M[2][3];
    }
}

// ---------------- launch ---------------------------------------------------
extern "C" void kernel_launch(void* const* d_in, const int* in_sizes, int n_in,
                              void* d_out, int out_size) {
    const float* x   = (const float*)d_in[0];
    const float* W1  = (const float*)d_in[1];
    const float* b1  = (const float*)d_in[2];
    const float* g1  = (const float*)d_in[3];
    const float* bt1 = (const float*)d_in[4];
    const float* W2  = (const float*)d_in[5];
    const float* b2  = (const float*)d_in[6];
    const float* g2  = (const float*)d_in[7];
    const float* bt2 = (const float*)d_in[8];
    const float* W3  = (const float*)d_in[9];
    const float* b3  = (const float*)d_in[10];
    const float* g3  = (const float*)d_in[11];
    const float* bt3 = (const float*)d_in[12];
    const float* W4  = (const float*)d_in[13];
    const float* b4  = (const float*)d_in[14];
    float* out = (float*)d_out;

    void *p_h2, *p_h3, *p_act, *p_w2t, *p_w3t, *p_ps, *p_pq, *p_sc, *p_sh;
    cudaGetSymbolAddress(&p_h2, g_h2);
    cudaGetSymbolAddress(&p_h3, g_h3);
    cudaGetSymbolAddress(&p_act, g_act);
    cudaGetSymbolAddress(&p_w2t, g_w2t);
    cudaGetSymbolAddress(&p_w3t, g_w3t);
    cudaGetSymbolAddress(&p_ps, g_ps);
    cudaGetSymbolAddress(&p_pq, g_pq);
    cudaGetSymbolAddress(&p_sc, g_scale);
    cudaGetSymbolAddress(&p_sh, g_shift);
    float* h2 = (float*)p_h2;
    float* h3 = (float*)p_h3;
    float* act = (float*)p_act;
    float* w2t = (float*)p_w2t;
    float* w3t = (float*)p_w3t;
    float* ps = (float*)p_ps;
    float* pq = (float*)p_pq;
    float* sc = (float*)p_sc;
    float* sh = (float*)p_sh;

    cudaFuncSetAttribute(k_gemm<false>, cudaFuncAttributeMaxDynamicSharedMemorySize,
                         GEMM_SMEM_BYTES);
    cudaFuncSetAttribute(k_gemm<true>, cudaFuncAttributeMaxDynamicSharedMemorySize,
                         GEMM_SMEM_BYTES);

    const dim3 gemmGrid(8, BB / 128);  // n fastest -> A L2 reuse

    // round weights to tf32 once per call
    k_cvtw<<<HD * HD / 4 / 256, 256>>>(W2, w2t);
    k_cvtw<<<HD * HD / 4 / 256, 256>>>(W3, w3t);

    // layer 1: stats only (no h1 materialization), then recompute+act
    k_layer1_stats<<<BB / 256, 256>>>(x, W1, b1, ps, pq);
    k_reduce2<<<HD, 256>>>(ps, pq, g1, bt1, sc, sh, BB / 256);
    k_act1<<<BB / 256, 256>>>(x, W1, b1, sc, sh, act);

    // layer 2: GEMM (A = precomputed tf32 act), fused column stats
    k_gemm<false><<<gemmGrid, 256, GEMM_SMEM_BYTES>>>(act, w2t, b2, nullptr,
                                                      nullptr, h2, ps, pq);
    k_reduce2<<<HD, 256>>>(ps, pq, g2, bt2, sc, sh, BB / 128);

    // layer 3: GEMM reads raw h2, BN+ReLU+tf32 fused at A-fragment load
    k_gemm<true><<<gemmGrid, 256, GEMM_SMEM_BYTES>>>(h2, w3t, b3, sc, sh, h3,
                                                     ps, pq);
    k_reduce2<<<HD, 256>>>(ps, pq, g3, bt3, sc, sh, BB / 128);

    // final layer (fp32, BN fused) + forward kinematics
    k_final<<<BB / 8, 256>>>(h3, sc, sh, W4, b4, out);
}

// round 13
// speedup vs baseline: 1.1077x; 1.1077x over previous
#include <cuda_runtime.h>
#include <math.h>
#include <stdint.h>

#define BB 131072
#define HD 1024

// ---------------- scratch (device globals; no allocation) ----------------
__device__ float g_h2[(size_t)BB * HD];   // 512MB: h2
__device__ float g_h3[(size_t)BB * HD];   // 512MB: h3
__device__ float g_act[(size_t)BB * HD];  // 512MB: layer-1 activations
__device__ float g_w2t[HD * HD];          // tf32-rounded W2
__device__ float g_w3t[HD * HD];          // tf32-rounded W3
__device__ float g_ps[1024 * HD];         // partial column sums
__device__ float g_pq[1024 * HD];         // partial column sumsq
__device__ float g_scale[HD];
__device__ float g_shift[HD];

// ---------------- helpers ----------------
__device__ __forceinline__ unsigned tf32_bits(float x) {
    unsigned u;
    asm("cvt.rna.tf32.f32 %0, %1;" : "=r"(u) : "f"(x));
    return u;
}

// ---------------- layer1 stats: partial sums of x@W1+b1 (no h store) ------
__global__ void k_layer1_stats(const float* __restrict__ x,
                               const float* __restrict__ W1,
                               const float* __restrict__ b1,
                               float* __restrict__ ps, float* __restrict__ pq) {
    __shared__ float xs[256 * 3];
    const int blk = blockIdx.x;
    const int tid = threadIdx.x;
    const int row0 = blk * 256;
    for (int i = tid; i < 768; i += 256) xs[i] = x[(size_t)row0 * 3 + i];
    __syncthreads();

    const int c = tid * 4;
    float w0[4], w1[4], w2[4], bb[4];
#pragma unroll
    for (int e = 0; e < 4; e++) {
        w0[e] = W1[c + e];
        w1[e] = W1[HD + c + e];
        w2[e] = W1[2 * HD + c + e];
        bb[e] = b1[c + e];
    }
    float s[4] = {0.f, 0.f, 0.f, 0.f}, q[4] = {0.f, 0.f, 0.f, 0.f};
    for (int r = 0; r < 256; r++) {
        float x0 = xs[3 * r], x1 = xs[3 * r + 1], x2 = xs[3 * r + 2];
#pragma unroll
        for (int e = 0; e < 4; e++) {
            float t = fmaf(x0, w0[e], bb[e]);
            t = fmaf(x1, w1[e], t);
            t = fmaf(x2, w2[e], t);
            s[e] += t;
            q[e] = fmaf(t, t, q[e]);
        }
    }
#pragma unroll
    for (int e = 0; e < 4; e++) {
        ps[(size_t)blk * HD + c + e] = s[e];
        pq[(size_t)blk * HD + c + e] = q[e];
    }
}

// ---------------- layer1 act: recompute h1 from x, BN+ReLU+tf32 -> act ----
__global__ void k_act1(const float* __restrict__ x, const float* __restrict__ W1,
                       const float* __restrict__ b1, const float* __restrict__ scale,
                       const float* __restrict__ shift, float* __restrict__ act) {
    __shared__ float xs[256 * 3];
    const int blk = blockIdx.x;
    const int tid = threadIdx.x;
    const int row0 = blk * 256;
    for (int i = tid; i < 768; i += 256) xs[i] = x[(size_t)row0 * 3 + i];
    __syncthreads();

    const int c = tid * 4;
    float w0[4], w1[4], w2[4], bb[4], sc[4], sh[4];
#pragma unroll
    for (int e = 0; e < 4; e++) {
        w0[e] = W1[c + e];
        w1[e] = W1[HD + c + e];
        w2[e] = W1[2 * HD + c + e];
        bb[e] = b1[c + e];
        sc[e] = scale[c + e];
        sh[e] = shift[c + e];
    }
    for (int r = 0; r < 256; r++) {
        float x0 = xs[3 * r], x1 = xs[3 * r + 1], x2 = xs[3 * r + 2];
        float v[4];
#pragma unroll
        for (int e = 0; e < 4; e++) {
            float t = fmaf(x0, w0[e], bb[e]);
            t = fmaf(x1, w1[e], t);
            t = fmaf(x2, w2[e], t);
            v[e] = __uint_as_float(tf32_bits(fmaxf(fmaf(t, sc[e], sh[e]), 0.f)));
        }
        *(float4*)(act + (size_t)(row0 + r) * HD + c) =
            make_float4(v[0], v[1], v[2], v[3]);
    }
}

// ---------------- reduce partials -> per-column scale/shift (1 blk/col) ---
__global__ void k_reduce2(const float* __restrict__ ps, const float* __restrict__ pq,
                          const float* __restrict__ g, const float* __restrict__ bt,
                          float* __restrict__ scale, float* __restrict__ shift,
                          int parts) {
    const int c = blockIdx.x;
    const int tid = threadIdx.x;
    float s = 0.f, q = 0.f;
    for (int p = tid; p < parts; p += 256) {
        s += ps[(size_t)p * HD + c];
        q += pq[(size_t)p * HD + c];
    }
    __shared__ float ss[8], qq[8];
#pragma unroll
    for (int o = 16; o; o >>= 1) {
        s += __shfl_xor_sync(0xffffffffu, s, o);
        q += __shfl_xor_sync(0xffffffffu, q, o);
    }
    if ((tid & 31) == 0) { ss[tid >> 5] = s; qq[tid >> 5] = q; }
    __syncthreads();
    if (tid == 0) {
        float S = 0.f, Q = 0.f;
#pragma unroll
        for (int w = 0; w < 8; w++) { S += ss[w]; Q += qq[w]; }
        const float invB = 1.0f / (float)BB;
        float mu = S * invB;
        float var = fmaxf(Q * invB - mu * mu, 0.f);
        float sc = g[c] * rsqrtf(var + 1e-5f);
        scale[c] = sc;
        shift[c] = bt[c] - mu * sc;
    }
}

// ---------------- weight round to tf32 ------------------------------------
__global__ void k_cvtw(const float* __restrict__ w, float* __restrict__ o) {
    const size_t i = (size_t)blockIdx.x * 256 + threadIdx.x;  // one float4
    float4 v = ((const float4*)w)[i];
    float4 r;
    r.x = __uint_as_float(tf32_bits(v.x));
    r.y = __uint_as_float(tf32_bits(v.y));
    r.z = __uint_as_float(tf32_bits(v.z));
    r.w = __uint_as_float(tf32_bits(v.w));
    ((float4*)o)[i] = r;
}

// ---------------- GEMM common config --------------------------------------
#define ASTR 36
#define BSTR 136
#define ASZ (128 * ASTR)  // 4608 floats
#define BSZ (32 * BSTR)   // 4352 floats
#define GEMM_SMEM_BYTES (2 * (ASZ + BSZ) * 4)          // 71680 (plain)
#define GEMMF_SMEM_BYTES ((2 * (ASZ + BSZ) + 2 * HD) * 4)  // 79872 (+sc/sh)

// Shared epilogue: store C = acc + bias, fused per-column sum/sumsq partials.
__device__ __forceinline__ void gemm_epilogue(
    float acc[4][4][4], const float* __restrict__ bias, float* __restrict__ C,
    float* __restrict__ ps, float* __restrict__ pq, float sred[8][32],
    float qred[8][32], int m0, int n0, int wm, int wn, int wid, int lane, int ly,
    int lx, int tid) {
    float sc_[4][2] = {{0.f, 0.f}, {0.f, 0.f}, {0.f, 0.f}, {0.f, 0.f}};
    float qc_[4][2] = {{0.f, 0.f}, {0.f, 0.f}, {0.f, 0.f}, {0.f, 0.f}};
#pragma unroll
    for (int mi = 0; mi < 4; mi++) {
        const int r0 = m0 + wm + mi * 16 + ly;
#pragma unroll
        for (int ni = 0; ni < 4; ni++) {
            const int c = n0 + wn + ni * 8 + 2 * lx;
            const float bc0 = bias[c], bc1 = bias[c + 1];
            float2 v0 = make_float2(acc[mi][ni][0] + bc0, acc[mi][ni][1] + bc1);
            float2 v1 = make_float2(acc[mi][ni][2] + bc0, acc[mi][ni][3] + bc1);
            *(float2*)(C + (size_t)r0 * HD + c) = v0;
            *(float2*)(C + (size_t)(r0 + 8) * HD + c) = v1;
            sc_[ni][0] += v0.x + v1.x;
            sc_[ni][1] += v0.y + v1.y;
            qc_[ni][0] = fmaf(v0.x, v0.x, fmaf(v1.x, v1.x, qc_[ni][0]));
            qc_[ni][1] = fmaf(v0.y, v0.y, fmaf(v1.y, v1.y, qc_[ni][1]));
        }
    }
#pragma unroll
    for (int ni = 0; ni < 4; ni++) {
#pragma unroll
        for (int j = 0; j < 2; j++) {
            float s = sc_[ni][j], q = qc_[ni][j];
#pragma unroll
            for (int o = 4; o <= 16; o <<= 1) {
                s += __shfl_xor_sync(0xffffffffu, s, o);
                q += __shfl_xor_sync(0xffffffffu, q, o);
            }
            if (lane < 4) {
                sred[wid][ni * 8 + 2 * lx + j] = s;
                qred[wid][ni * 8 + 2 * lx + j] = q;
            }
        }
    }
    __syncthreads();
    if (tid < 128) {
        const int col = tid;
        const int gpair = (col >> 5) * 2;
        const int cc = col & 31;
        ps[(size_t)blockIdx.y * HD + n0 + col] = sred[gpair][cc] + sred[gpair + 1][cc];
        pq[(size_t)blockIdx.y * HD + n0 + col] = qred[gpair][cc] + qred[gpair + 1][cc];
    }
}

// Shared compute for one 32-wide K tile from smem stages.
__device__ __forceinline__ void gemm_tile_compute(const float* As, const float* Bs,
                                                  float acc[4][4][4], int wm, int wn,
                                                  int ly, int lx) {
#pragma unroll
    for (int kk = 0; kk < 32; kk += 8) {
        unsigned af[4][4], bf[4][2];
#pragma unroll
        for (int mi = 0; mi < 4; mi++) {
            const float* p = As + (wm + mi * 16 + ly) * ASTR + kk + lx;
            af[mi][0] = __float_as_uint(p[0]);
            af[mi][1] = __float_as_uint(p[8 * ASTR]);
            af[mi][2] = __float_as_uint(p[4]);
            af[mi][3] = __float_as_uint(p[8 * ASTR + 4]);
        }
#pragma unroll
        for (int ni = 0; ni < 4; ni++) {
            const float* p = Bs + (kk + lx) * BSTR + wn + ni * 8 + ly;
            bf[ni][0] = __float_as_uint(p[0]);
            bf[ni][1] = __float_as_uint(p[4 * BSTR]);
        }
#pragma unroll
        for (int mi = 0; mi < 4; mi++)
#pragma unroll
            for (int ni = 0; ni < 4; ni++) {
                asm volatile(
                    "mma.sync.aligned.m16n8k8.row.col.f32.tf32.tf32.f32 "
                    "{%0,%1,%2,%3}, {%4,%5,%6,%7}, {%8,%9}, {%0,%1,%2,%3};"
                    : "+f"(acc[mi][ni][0]), "+f"(acc[mi][ni][1]),
                      "+f"(acc[mi][ni][2]), "+f"(acc[mi][ni][3])
                    : "r"(af[mi][0]), "r"(af[mi][1]), "r"(af[mi][2]), "r"(af[mi][3]),
                      "r"(bf[ni][0]), "r"(bf[ni][1]));
            }
    }
}

// ---------------- plain GEMM (exact 3812us mainloop): C = A@W + bias ------
__global__ void __launch_bounds__(256, 2)
k_gemm(const float* __restrict__ A, const float* __restrict__ Bw,
       const float* __restrict__ bias, float* __restrict__ C,
       float* __restrict__ ps, float* __restrict__ pq) {
    extern __shared__ float sm[];
    __shared__ float sred[8][32], qred[8][32];
    const int tid = threadIdx.x;
    const int m0 = blockIdx.y * 128;
    const int n0 = blockIdx.x * 128;

    const unsigned smA = (unsigned)__cvta_generic_to_shared(sm);
    const unsigned smB = smA + 2u * ASZ * 4u;

    const int ar = tid >> 3, aq = tid & 7;
    const int br = tid >> 5, bq = tid & 31;

    const float* Ag = A + (size_t)(m0 + ar) * HD + aq * 4;
    const float* Bg = Bw + (size_t)br * HD + n0 + bq * 4;
    const unsigned aS = (unsigned)(ar * ASTR + aq * 4) * 4u;
    const unsigned bS = (unsigned)(br * BSTR + bq * 4) * 4u;

    auto load_tile = [&](int stage, int k0) {
        unsigned a_s = smA + (unsigned)stage * (ASZ * 4u) + aS;
        const float* a_g = Ag + k0;
#pragma unroll
        for (int j = 0; j < 4; j++) {
            asm volatile("cp.async.cg.shared.global [%0], [%1], 16;" ::"r"(
                             a_s + (unsigned)(j * 32 * ASTR * 4)),
                         "l"(a_g + (size_t)32 * HD * j));
        }
        unsigned b_s = smB + (unsigned)stage * (BSZ * 4u) + bS;
        const float* b_g = Bg + (size_t)k0 * HD;
#pragma unroll
        for (int j = 0; j < 4; j++) {
            asm volatile("cp.async.cg.shared.global [%0], [%1], 16;" ::"r"(
                             b_s + (unsigned)(j * 8 * BSTR * 4)),
                         "l"(b_g + (size_t)8 * HD * j));
        }
        asm volatile("cp.async.commit_group;");
    };

    float acc[4][4][4];
#pragma unroll
    for (int a = 0; a < 4; a++)
#pragma unroll
        for (int b = 0; b < 4; b++)
#pragma unroll
            for (int c = 0; c < 4; c++) acc[a][b][c] = 0.f;

    const int lane = tid & 31, ly = lane >> 2, lx = lane & 3;
    const int wid = tid >> 5;
    const int wm = (wid & 1) * 64;
    const int wn = (tid >> 6) * 32;

    load_tile(0, 0);
#pragma unroll 1
    for (int t = 0; t < 32; t++) {
        if (t < 31) {
            load_tile((t + 1) & 1, (t + 1) * 32);
            asm volatile("cp.async.wait_group 1;");
        } else {
            asm volatile("cp.async.wait_group 0;");
        }
        __syncthreads();
        gemm_tile_compute(sm + (t & 1) * ASZ, sm + 2 * ASZ + (t & 1) * BSZ, acc,
                          wm, wn, ly, lx);
        __syncthreads();
    }
    gemm_epilogue(acc, bias, C, ps, pq, sred, qred, m0, n0, wm, wn, wid, lane,
                  ly, lx, tid);
}

// ---------------- fused GEMM: C = act(A)@W + bias --------------------------
// A holds raw pre-BN values. A path: LDG.128 -> registers -> BN+ReLU+tf32
// transform (bit-identical to k_act arithmetic) -> STS. Transform runs once
// per A ELEMENT (not per fragment read), scale/shift served from smem.
// B path: cp.async double-buffer, identical to plain kernel.
__global__ void __launch_bounds__(256, 2)
k_gemm_f(const float* __restrict__ A, const float* __restrict__ Bw,
         const float* __restrict__ bias, const float* __restrict__ scA,
         const float* __restrict__ shA, float* __restrict__ C,
         float* __restrict__ ps, float* __restrict__ pq) {
    extern __shared__ float sm[];
    __shared__ float sred[8][32], qred[8][32];
    const int tid = threadIdx.x;
    const int m0 = blockIdx.y * 128;
    const int n0 = blockIdx.x * 128;

    float* s_sc = sm + 2 * ASZ + 2 * BSZ;
    float* s_sh = s_sc + HD;

    const unsigned smB = (unsigned)__cvta_generic_to_shared(sm) + 2u * ASZ * 4u;

    const int ar = tid >> 3, aq = tid & 7;
    const int br = tid >> 5, bq = tid & 31;

    const float* Ag = A + (size_t)(m0 + ar) * HD + aq * 4;
    const float* Bg = Bw + (size_t)br * HD + n0 + bq * 4;
    const unsigned bS = (unsigned)(br * BSTR + bq * 4) * 4u;

    // preload scale/shift into smem (consumed by every tile's transform)
    for (int i = tid; i < HD; i += 256) {
        s_sc[i] = scA[i];
        s_sh[i] = shA[i];
    }

    float4 av[4];
    auto ldgA = [&](int t) {
#pragma unroll
        for (int j = 0; j < 4; j++)
            av[j] = *(const float4*)(Ag + (size_t)32 * HD * j + t * 32);
    };
    auto stsA = [&](int stage, int t) {
        const float4 scv = *(const float4*)(s_sc + t * 32 + aq * 4);
        const float4 shv = *(const float4*)(s_sh + t * 32 + aq * 4);
        float* dst = sm + stage * ASZ + ar * ASTR + aq * 4;
#pragma unroll
        for (int j = 0; j < 4; j++) {
            float4 v = av[j], o;
            o.x = __uint_as_float(tf32_bits(fmaxf(fmaf(v.x, scv.x, shv.x), 0.f)));
            o.y = __uint_as_float(tf32_bits(fmaxf(fmaf(v.y, scv.y, shv.y), 0.f)));
            o.z = __uint_as_float(tf32_bits(fmaxf(fmaf(v.z, scv.z, shv.z), 0.f)));
            o.w = __uint_as_float(tf32_bits(fmaxf(fmaf(v.w, scv.w, shv.w), 0.f)));
            *(float4*)(dst + j * 32 * ASTR) = o;
        }
    };
    auto ldB = [&](int stage, int k0) {
        unsigned b_s = smB + (unsigned)stage * (BSZ * 4u) + bS;
        const float* b_g = Bg + (size_t)k0 * HD;
#pragma unroll
        for (int j = 0; j < 4; j++) {
            asm volatile("cp.async.cg.shared.global [%0], [%1], 16;" ::"r"(
                             b_s + (unsigned)(j * 8 * BSTR * 4)),
                         "l"(b_g + (size_t)8 * HD * j));
        }
        asm volatile("cp.async.commit_group;");
    };

    float acc[4][4][4];
#pragma unroll
    for (int a = 0; a < 4; a++)
#pragma unroll
        for (int b = 0; b < 4; b++)
#pragma unroll
            for (int c = 0; c < 4; c++) acc[a][b][c] = 0.f;

    const int lane = tid & 31, ly = lane >> 2, lx = lane & 3;
    const int wid = tid >> 5;
    const int wm = (wid & 1) * 64;
    const int wn = (tid >> 6) * 32;

    // prologue: B tile 0 in flight; A tile 0 transformed into stage 0;
    // A tile 1 raw in registers.
    ldB(0, 0);
    ldgA(0);
    __syncthreads();  // s_sc/s_sh visible before first transform
    stsA(0, 0);
    ldgA(1);

#pragma unroll 1
    for (int t = 0; t < 32; t++) {
        if (t < 31) {
            ldB((t + 1) & 1, (t + 1) * 32);
            asm volatile("cp.async.wait_group 1;");
        } else {
            asm volatile("cp.async.wait_group 0;");
        }
        __syncthreads();  // B[t] + stsA(t) visible; compute(t-1) finished
        if (t < 31) {
            stsA((t + 1) & 1, t + 1);  // safe: that buffer last read at t-1
            if (t < 30) ldgA(t + 2);   // latency covered by compute(t)
        }
        gemm_tile_compute(sm + (t & 1) * ASZ, sm + 2 * ASZ + (t & 1) * BSZ, acc,
                          wm, wn, ly, lx);
        __syncthreads();  // stage t&1 free before stsA at t+1 overwrites it
    }
    gemm_epilogue(acc, bias, C, ps, pq, sred, qred, m0, n0, wm, wn, wid, lane,
                  ly, lx, tid);
}

// ---------------- final: thetas = relu(bn(h3)) @ W4 + b4; kinematics ------
__device__ __forceinline__ void dh_mat(float M[3][4], float th, float r, float ca,
                                       float sa) {
    float ct = cosf(th), st = sinf(th);
    M[0][0] = ct;  M[0][1] = -st * ca; M[0][2] = st * sa;  M[0][3] = r * ct;
    M[1][0] = st;  M[1][1] = ct * ca;  M[1][2] = -ct * sa; M[1][3] = r * st;
    M[2][0] = 0.f; M[2][1] = sa;       M[2][2] = ca;       M[2][3] = 0.f;
}

__device__ __forceinline__ void matmul34(const float A[3][4], const float Bm[3][4],
                                         float C[3][4]) {
#pragma unroll
    for (int i = 0; i < 3; i++) {
#pragma unroll
        for (int j = 0; j < 4; j++) {
            float v = A[i][0] * Bm[0][j] + A[i][1] * Bm[1][j] + A[i][2] * Bm[2][j];
            if (j == 3) v += A[i][3];
            C[i][j] = v;
        }
    }
}

__global__ void k_final(const float* __restrict__ h3, const float* __restrict__ scale,
                        const float* __restrict__ shift, const float* __restrict__ W4,
                        const float* __restrict__ b4, float* __restrict__ out) {
    __shared__ float w4s[3072];
    __shared__ float b4s[3];
    const int tid = threadIdx.x;
    for (int i = tid; i < 3072; i += 256) w4s[i] = W4[i];
    if (tid < 3) b4s[tid] = b4[tid];
    __syncthreads();

    const int lane = tid & 31;
    const size_t row = (size_t)blockIdx.x * 8 + (tid >> 5);
    const float* hr = h3 + row * HD;
    float t0 = 0.f, t1 = 0.f, t2 = 0.f;
    for (int k = lane; k < HD; k += 32) {
        float a = fmaxf(fmaf(hr[k], scale[k], shift[k]), 0.f);
        t0 = fmaf(a, w4s[3 * k + 0], t0);
        t1 = fmaf(a, w4s[3 * k + 1], t1);
        t2 = fmaf(a, w4s[3 * k + 2], t2);
    }
#pragma unroll
    for (int o = 16; o > 0; o >>= 1) {
        t0 += __shfl_xor_sync(0xffffffffu, t0, o);
        t1 += __shfl_xor_sync(0xffffffffu, t1, o);
        t2 += __shfl_xor_sync(0xffffffffu, t2, o);
    }
    if (lane == 0) {
        const float th0 = t0 + b4s[0];
        const float th1 = t1 + b4s[1];
        const float th2 = t2 + b4s[2];
        out[row * 3 + 0] = th0;
        out[row * 3 + 1] = th1;
        out[row * 3 + 2] = th2;

        const float PI2 = 1.57079632679489661923f;
        float M[3][4], Nn[3][4], P[3][4];
        dh_mat(M, th0, 0.f, cosf(PI2), sinf(PI2));
        dh_mat(Nn, th1, 0.12f, 1.f, 0.f);
        matmul34(M, Nn, P);
        dh_mat(Nn, th2, 0.115f, 1.f, 0.f);
        matmul34(P, Nn, M);
        float* op = out + (size_t)BB * 3 + row * 3;
        op[0] = M[0][3];
        op[1] = M[1][3];
        op[2] = M[2][3];
    }
}

// ---------------- launch ---------------------------------------------------
extern "C" void kernel_launch(void* const* d_in, const int* in_sizes, int n_in,
                              void* d_out, int out_size) {
    const float* x   = (const float*)d_in[0];
    const float* W1  = (const float*)d_in[1];
    const float* b1  = (const float*)d_in[2];
    const float* g1  = (const float*)d_in[3];
    const float* bt1 = (const float*)d_in[4];
    const float* W2  = (const float*)d_in[5];
    const float* b2  = (const float*)d_in[6];
    const float* g2  = (const float*)d_in[7];
    const float* bt2 = (const float*)d_in[8];
    const float* W3  = (const float*)d_in[9];
    const float* b3  = (const float*)d_in[10];
    const float* g3  = (const float*)d_in[11];
    const float* bt3 = (const float*)d_in[12];
    const float* W4  = (const float*)d_in[13];
    const float* b4  = (const float*)d_in[14];
    float* out = (float*)d_out;

    void *p_h2, *p_h3, *p_act, *p_w2t, *p_w3t, *p_ps, *p_pq, *p_sc, *p_sh;
    cudaGetSymbolAddress(&p_h2, g_h2);
    cudaGetSymbolAddress(&p_h3, g_h3);
    cudaGetSymbolAddress(&p_act, g_act);
    cudaGetSymbolAddress(&p_w2t, g_w2t);
    cudaGetSymbolAddress(&p_w3t, g_w3t);
    cudaGetSymbolAddress(&p_ps, g_ps);
    cudaGetSymbolAddress(&p_pq, g_pq);
    cudaGetSymbolAddress(&p_sc, g_scale);
    cudaGetSymbolAddress(&p_sh, g_shift);
    float* h2 = (float*)p_h2;
    float* h3 = (float*)p_h3;
    float* act = (float*)p_act;
    float* w2t = (float*)p_w2t;
    float* w3t = (float*)p_w3t;
    float* ps = (float*)p_ps;
    float* pq = (float*)p_pq;
    float* sc = (float*)p_sc;
    float* sh = (float*)p_sh;

    cudaFuncSetAttribute(k_gemm, cudaFuncAttributeMaxDynamicSharedMemorySize,
                         GEMM_SMEM_BYTES);
    cudaFuncSetAttribute(k_gemm_f, cudaFuncAttributeMaxDynamicSharedMemorySize,
                         GEMMF_SMEM_BYTES);

    const dim3 gemmGrid(8, BB / 128);  // n fastest -> A L2 reuse

    // round weights to tf32 once per call
    k_cvtw<<<HD * HD / 4 / 256, 256>>>(W2, w2t);
    k_cvtw<<<HD * HD / 4 / 256, 256>>>(W3, w3t);

    // layer 1: stats only (no h1 materialization), then recompute+act
    k_layer1_stats<<<BB / 256, 256>>>(x, W1, b1, ps, pq);
    k_reduce2<<<HD, 256>>>(ps, pq, g1, bt1, sc, sh, BB / 256);
    k_act1<<<BB / 256, 256>>>(x, W1, b1, sc, sh, act);

    // layer 2: plain GEMM (A = precomputed tf32 act), fused column stats
    k_gemm<<<gemmGrid, 256, GEMM_SMEM_BYTES>>>(act, w2t, b2, h2, ps, pq);
    k_reduce2<<<HD, 256>>>(ps, pq, g2, bt2, sc, sh, BB / 128);

    // layer 3: fused GEMM reads raw h2, BN+ReLU+tf32 applied at A smem-store
    k_gemm_f<<<gemmGrid, 256, GEMMF_SMEM_BYTES>>>(h2, w3t, b3, sc, sh, h3, ps, pq);
    k_reduce2<<<HD, 256>>>(ps, pq, g3, bt3, sc, sh, BB / 128);

    // final layer (fp32, BN fused) + forward kinematics
    k_final<<<BB / 8, 256>>>(h3, sc, sh, W4, b4, out);
}

// round 14
// speedup vs baseline: 1.6486x; 1.4883x over previous
#include <cuda_runtime.h>
#include <cuda_fp16.h>
#include <math.h>
#include <stdint.h>

#define BB 131072
#define HD 1024

// ---------------- scratch (device globals; no allocation) ----------------
__device__ float g_h2[(size_t)BB * HD];            // 512MB: h2 (fp32)
__device__ float g_h3[(size_t)BB * HD];            // 512MB: h3 (fp32)
__device__ unsigned g_acth[(size_t)BB * HD / 2];   // 256MB: layer1 act fp16 (half2)
__device__ unsigned g_w2p[(HD / 2) * HD];          // W2 packed half2 [k/2][n]
__device__ unsigned g_w3p[(HD / 2) * HD];          // W3 packed half2 [k/2][n]
__device__ float g_ps[1024 * HD];
__device__ float g_pq[1024 * HD];
__device__ float g_scale[HD];
__device__ float g_shift[HD];

// ---------------- helpers ----------------
// pack two fp32 into half2 bits: low 16 = a, high 16 = b (RNE)
__device__ __forceinline__ unsigned pack_h2(float a, float b) {
    unsigned u;
    asm("{\n\t.reg .f16 lo, hi;\n\t"
        "cvt.rn.f16.f32 lo, %1;\n\t"
        "cvt.rn.f16.f32 hi, %2;\n\t"
        "mov.b32 %0, {lo, hi};\n\t}"
        : "=r"(u) : "f"(a), "f"(b));
    return u;
}

// ---------------- layer1 stats: partial sums of x@W1+b1 (no h store) ------
__global__ void k_layer1_stats(const float* __restrict__ x,
                               const float* __restrict__ W1,
                               const float* __restrict__ b1,
                               float* __restrict__ ps, float* __restrict__ pq) {
    __shared__ float xs[256 * 3];
    const int blk = blockIdx.x;
    const int tid = threadIdx.x;
    const int row0 = blk * 256;
    for (int i = tid; i < 768; i += 256) xs[i] = x[(size_t)row0 * 3 + i];
    __syncthreads();

    const int c = tid * 4;
    float w0[4], w1[4], w2[4], bb[4];
#pragma unroll
    for (int e = 0; e < 4; e++) {
        w0[e] = W1[c + e];
        w1[e] = W1[HD + c + e];
        w2[e] = W1[2 * HD + c + e];
        bb[e] = b1[c + e];
    }
    float s[4] = {0.f, 0.f, 0.f, 0.f}, q[4] = {0.f, 0.f, 0.f, 0.f};
    for (int r = 0; r < 256; r++) {
        float x0 = xs[3 * r], x1 = xs[3 * r + 1], x2 = xs[3 * r + 2];
#pragma unroll
        for (int e = 0; e < 4; e++) {
            float t = fmaf(x0, w0[e], bb[e]);
            t = fmaf(x1, w1[e], t);
            t = fmaf(x2, w2[e], t);
            s[e] += t;
            q[e] = fmaf(t, t, q[e]);
        }
    }
#pragma unroll
    for (int e = 0; e < 4; e++) {
        ps[(size_t)blk * HD + c + e] = s[e];
        pq[(size_t)blk * HD + c + e] = q[e];
    }
}

// ---------------- layer1 act: recompute h1, BN+ReLU -> fp16 act -----------
__global__ void k_act1(const float* __restrict__ x, const float* __restrict__ W1,
                       const float* __restrict__ b1, const float* __restrict__ scale,
                       const float* __restrict__ shift, unsigned* __restrict__ acth) {
    __shared__ float xs[256 * 3];
    const int blk = blockIdx.x;
    const int tid = threadIdx.x;
    const int row0 = blk * 256;
    for (int i = tid; i < 768; i += 256) xs[i] = x[(size_t)row0 * 3 + i];
    __syncthreads();

    const int c = tid * 4;
    float w0[4], w1[4], w2[4], bb[4], sc[4], sh[4];
#pragma unroll
    for (int e = 0; e < 4; e++) {
        w0[e] = W1[c + e];
        w1[e] = W1[HD + c + e];
        w2[e] = W1[2 * HD + c + e];
        bb[e] = b1[c + e];
        sc[e] = scale[c + e];
        sh[e] = shift[c + e];
    }
    for (int r = 0; r < 256; r++) {
        float x0 = xs[3 * r], x1 = xs[3 * r + 1], x2 = xs[3 * r + 2];
        float v[4];
#pragma unroll
        for (int e = 0; e < 4; e++) {
            float t = fmaf(x0, w0[e], bb[e]);
            t = fmaf(x1, w1[e], t);
            t = fmaf(x2, w2[e], t);
            v[e] = fmaxf(fmaf(t, sc[e], sh[e]), 0.f);
        }
        ((uint2*)acth)[(size_t)(row0 + r) * 256 + tid] =
            make_uint2(pack_h2(v[0], v[1]), pack_h2(v[2], v[3]));
    }
}

// ---------------- reduce partials -> per-column scale/shift (1 blk/col) ---
__global__ void k_reduce2(const float* __restrict__ ps, const float* __restrict__ pq,
                          const float* __restrict__ g, const float* __restrict__ bt,
                          float* __restrict__ scale, float* __restrict__ shift,
                          int parts) {
    const int c = blockIdx.x;
    const int tid = threadIdx.x;
    float s = 0.f, q = 0.f;
    for (int p = tid; p < parts; p += 256) {
        s += ps[(size_t)p * HD + c];
        q += pq[(size_t)p * HD + c];
    }
    __shared__ float ss[8], qq[8];
#pragma unroll
    for (int o = 16; o; o >>= 1) {
        s += __shfl_xor_sync(0xffffffffu, s, o);
        q += __shfl_xor_sync(0xffffffffu, q, o);
    }
    if ((tid & 31) == 0) { ss[tid >> 5] = s; qq[tid >> 5] = q; }
    __syncthreads();
    if (tid == 0) {
        float S = 0.f, Q = 0.f;
#pragma unroll
        for (int w = 0; w < 8; w++) { S += ss[w]; Q += qq[w]; }
        const float invB = 1.0f / (float)BB;
        float mu = S * invB;
        float var = fmaxf(Q * invB - mu * mu, 0.f);
        float sc = g[c] * rsqrtf(var + 1e-5f);
        scale[c] = sc;
        shift[c] = bt[c] - mu * sc;
    }
}

// ---------------- weight: fp32 -> packed half2 [k/2][n] -------------------
__global__ void k_cvtwp(const float* __restrict__ w, unsigned* __restrict__ o) {
    const int n = blockIdx.x * 256 + threadIdx.x;
    const int k2 = blockIdx.y;
    o[(size_t)k2 * HD + n] =
        pack_h2(w[(size_t)(2 * k2) * HD + n], w[(size_t)(2 * k2 + 1) * HD + n]);
}

// ---------------- fp16 GEMM config ----------------------------------------
// CTA tile 128x128x32, 8 warps (2x4), m16n8k16 f16 mma.sync (fp32 accum),
// cp.async 2-stage. A smem: 128 rows x 16 half2 words, stride 20 words
// (20*ly+lx distinct mod 32 -> conflict-free fragment loads). B smem:
// 16 k-pair rows x 128 half2 words, stride 136 (8*lx+ly distinct).
#define AW 20
#define BW 136
#define ASZW (128 * AW)  // 2560 words
#define BSZW (16 * BW)   // 2176 words
#define GEMM_SMEM_H (2 * (ASZW + BSZW) * 4)       // 37888
#define GEMMF_SMEM_H (GEMM_SMEM_H + 2 * HD * 4)   // 46080

// Shared epilogue: store C = acc + bias, fused per-column sum/sumsq partials.
__device__ __forceinline__ void gemm_epilogue(
    float acc[4][4][4], const float* __restrict__ bias, float* __restrict__ C,
    float* __restrict__ ps, float* __restrict__ pq, float sred[8][32],
    float qred[8][32], int m0, int n0, int wm, int wn, int wid, int lane, int ly,
    int lx, int tid) {
    float sc_[4][2] = {{0.f, 0.f}, {0.f, 0.f}, {0.f, 0.f}, {0.f, 0.f}};
    float qc_[4][2] = {{0.f, 0.f}, {0.f, 0.f}, {0.f, 0.f}, {0.f, 0.f}};
#pragma unroll
    for (int mi = 0; mi < 4; mi++) {
        const int r0 = m0 + wm + mi * 16 + ly;
#pragma unroll
        for (int ni = 0; ni < 4; ni++) {
            const int c = n0 + wn + ni * 8 + 2 * lx;
            const float bc0 = bias[c], bc1 = bias[c + 1];
            float2 v0 = make_float2(acc[mi][ni][0] + bc0, acc[mi][ni][1] + bc1);
            float2 v1 = make_float2(acc[mi][ni][2] + bc0, acc[mi][ni][3] + bc1);
            *(float2*)(C + (size_t)r0 * HD + c) = v0;
            *(float2*)(C + (size_t)(r0 + 8) * HD + c) = v1;
            sc_[ni][0] += v0.x + v1.x;
            sc_[ni][1] += v0.y + v1.y;
            qc_[ni][0] = fmaf(v0.x, v0.x, fmaf(v1.x, v1.x, qc_[ni][0]));
            qc_[ni][1] = fmaf(v0.y, v0.y, fmaf(v1.y, v1.y, qc_[ni][1]));
        }
    }
#pragma unroll
    for (int ni = 0; ni < 4; ni++) {
#pragma unroll
        for (int j = 0; j < 2; j++) {
            float s = sc_[ni][j], q = qc_[ni][j];
#pragma unroll
            for (int o = 4; o <= 16; o <<= 1) {
                s += __shfl_xor_sync(0xffffffffu, s, o);
                q += __shfl_xor_sync(0xffffffffu, q, o);
            }
            if (lane < 4) {
                sred[wid][ni * 8 + 2 * lx + j] = s;
                qred[wid][ni * 8 + 2 * lx + j] = q;
            }
        }
    }
    __syncthreads();
    if (tid < 128) {
        const int col = tid;
        const int gpair = (col >> 5) * 2;
        const int cc = col & 31;
        ps[(size_t)blockIdx.y * HD + n0 + col] = sred[gpair][cc] + sred[gpair + 1][cc];
        pq[(size_t)blockIdx.y * HD + n0 + col] = qred[gpair][cc] + qred[gpair + 1][cc];
    }
}

// One K=32 tile: two k16 groups, 32 m16n8k16 MMAs per warp.
__device__ __forceinline__ void gemm_tile_h(const unsigned* As, const unsigned* Bs,
                                            float acc[4][4][4], int wm, int wn,
                                            int ly, int lx) {
#pragma unroll
    for (int kk2 = 0; kk2 < 16; kk2 += 8) {
        unsigned af[4][4], bf[4][2];
#pragma unroll
        for (int mi = 0; mi < 4; mi++) {
            const unsigned* p = As + (wm + mi * 16 + ly) * AW + kk2 + lx;
            af[mi][0] = p[0];
            af[mi][1] = p[8 * AW];
            af[mi][2] = p[4];
            af[mi][3] = p[8 * AW + 4];
        }
#pragma unroll
        for (int ni = 0; ni < 4; ni++) {
            const unsigned* p = Bs + (kk2 + lx) * BW + wn + ni * 8 + ly;
            bf[ni][0] = p[0];
            bf[ni][1] = p[4 * BW];
        }
#pragma unroll
        for (int mi = 0; mi < 4; mi++)
#pragma unroll
            for (int ni = 0; ni < 4; ni++) {
                asm volatile(
                    "mma.sync.aligned.m16n8k16.row.col.f32.f16.f16.f32 "
                    "{%0,%1,%2,%3}, {%4,%5,%6,%7}, {%8,%9}, {%0,%1,%2,%3};"
                    : "+f"(acc[mi][ni][0]), "+f"(acc[mi][ni][1]),
                      "+f"(acc[mi][ni][2]), "+f"(acc[mi][ni][3])
                    : "r"(af[mi][0]), "r"(af[mi][1]), "r"(af[mi][2]), "r"(af[mi][3]),
                      "r"(bf[ni][0]), "r"(bf[ni][1]));
            }
    }
}

// ---------------- plain fp16 GEMM: C = Ah@W + bias (A = fp16 act) ---------
__global__ void __launch_bounds__(256, 2)
k_gemm(const unsigned* __restrict__ Ah, const unsigned* __restrict__ Bp,
       const float* __restrict__ bias, float* __restrict__ C,
       float* __restrict__ ps, float* __restrict__ pq) {
    extern __shared__ float sm[];
    __shared__ float sred[8][32], qred[8][32];
    const int tid = threadIdx.x;
    const int m0 = blockIdx.y * 128;
    const int n0 = blockIdx.x * 128;

    const unsigned smA = (unsigned)__cvta_generic_to_shared(sm);
    const unsigned smB = smA + 2u * ASZW * 4u;

    const int arow = tid >> 2, aq = tid & 3;   // A: rows arow, arow+64; chunk aq
    const int brow = tid >> 4, bc = tid & 15;  // B: row brow; chunks bc, bc+16

    const unsigned* Agw = Ah + (size_t)(m0 + arow) * (HD / 2) + aq * 4;
    const unsigned aSb = (unsigned)(arow * AW * 4 + aq * 16);
    const unsigned bSb = (unsigned)(brow * BW * 4 + bc * 16);

    auto load_tile = [&](int stage, int t) {
        unsigned a_s = smA + (unsigned)stage * (ASZW * 4u) + aSb;
        const unsigned* a_g = Agw + t * 16;
#pragma unroll
        for (int j = 0; j < 2; j++) {
            asm volatile("cp.async.cg.shared.global [%0], [%1], 16;"
                         :: "r"(a_s + (unsigned)(j * 64 * AW * 4)),
                            "l"(a_g + (size_t)64 * (HD / 2) * j));
        }
        unsigned b_s = smB + (unsigned)stage * (BSZW * 4u) + bSb;
        const unsigned* b_g = Bp + (size_t)(t * 16 + brow) * HD + n0 + bc * 4;
#pragma unroll
        for (int j = 0; j < 2; j++) {
            asm volatile("cp.async.cg.shared.global [%0], [%1], 16;"
                         :: "r"(b_s + (unsigned)(j * 256)), "l"(b_g + j * 64));
        }
        asm volatile("cp.async.commit_group;");
    };

    float acc[4][4][4];
#pragma unroll
    for (int a = 0; a < 4; a++)
#pragma unroll
        for (int b = 0; b < 4; b++)
#pragma unroll
            for (int c = 0; c < 4; c++) acc[a][b][c] = 0.f;

    const int lane = tid & 31, ly = lane >> 2, lx = lane & 3;
    const int wid = tid >> 5;
    const int wm = (wid & 1) * 64;
    const int wn = (tid >> 6) * 32;

    load_tile(0, 0);
#pragma unroll 1
    for (int t = 0; t < 32; t++) {
        if (t < 31) {
            load_tile((t + 1) & 1, t + 1);
            asm volatile("cp.async.wait_group 1;");
        } else {
            asm volatile("cp.async.wait_group 0;");
        }
        __syncthreads();
        gemm_tile_h((const unsigned*)sm + (t & 1) * ASZW,
                    (const unsigned*)sm + 2 * ASZW + (t & 1) * BSZW, acc, wm, wn,
                    ly, lx);
        __syncthreads();
    }
    gemm_epilogue(acc, bias, C, ps, pq, sred, qred, m0, n0, wm, wn, wid, lane,
                  ly, lx, tid);
}

// ---------------- fused fp16 GEMM: C = act(A)@W + bias --------------------
// A holds raw fp32 pre-BN values; LDG.128 -> BN+ReLU -> fp16 -> STS.128.
// Transform runs once per element; scale/shift live in smem.
__global__ void __launch_bounds__(256, 2)
k_gemm_f(const float* __restrict__ A, const unsigned* __restrict__ Bp,
         const float* __restrict__ bias, const float* __restrict__ scA,
         const float* __restrict__ shA, float* __restrict__ C,
         float* __restrict__ ps, float* __restrict__ pq) {
    extern __shared__ float sm[];
    __shared__ float sred[8][32], qred[8][32];
    const int tid = threadIdx.x;
    const int m0 = blockIdx.y * 128;
    const int n0 = blockIdx.x * 128;

    float* s_sc = sm + 2 * (ASZW + BSZW);
    float* s_sh = s_sc + HD;

    const unsigned smB = (unsigned)__cvta_generic_to_shared(sm) + 2u * ASZW * 4u;

    const int frow = tid >> 2, fq = tid & 3;   // rows frow, frow+64; cols fq*8..+7
    const int brow = tid >> 4, bc = tid & 15;
    const unsigned bSb = (unsigned)(brow * BW * 4 + bc * 16);

    for (int i = tid; i < HD; i += 256) {
        s_sc[i] = scA[i];
        s_sh[i] = shA[i];
    }

    float4 av[2][2];
    auto ldgA = [&](int t) {
#pragma unroll
        for (int j = 0; j < 2; j++) {
            const float* src = A + (size_t)(m0 + frow + 64 * j) * HD + t * 32 + fq * 8;
            av[j][0] = *(const float4*)src;
            av[j][1] = *(const float4*)(src + 4);
        }
    };
    auto stsA = [&](int stage, int t) {
        const float4 sc0 = *(const float4*)(s_sc + t * 32 + fq * 8);
        const float4 sc1 = *(const float4*)(s_sc + t * 32 + fq * 8 + 4);
        const float4 sh0 = *(const float4*)(s_sh + t * 32 + fq * 8);
        const float4 sh1 = *(const float4*)(s_sh + t * 32 + fq * 8 + 4);
#pragma unroll
        for (int j = 0; j < 2; j++) {
            float4 v0 = av[j][0], v1 = av[j][1];
            float o0 = fmaxf(fmaf(v0.x, sc0.x, sh0.x), 0.f);
            float o1 = fmaxf(fmaf(v0.y, sc0.y, sh0.y), 0.f);
            float o2 = fmaxf(fmaf(v0.z, sc0.z, sh0.z), 0.f);
            float o3 = fmaxf(fmaf(v0.w, sc0.w, sh0.w), 0.f);
            float o4 = fmaxf(fmaf(v1.x, sc1.x, sh1.x), 0.f);
            float o5 = fmaxf(fmaf(v1.y, sc1.y, sh1.y), 0.f);
            float o6 = fmaxf(fmaf(v1.z, sc1.z, sh1.z), 0.f);
            float o7 = fmaxf(fmaf(v1.w, sc1.w, sh1.w), 0.f);
            uint4 uu;
            uu.x = pack_h2(o0, o1);
            uu.y = pack_h2(o2, o3);
            uu.z = pack_h2(o4, o5);
            uu.w = pack_h2(o6, o7);
            *(uint4*)((char*)sm + (size_t)stage * (ASZW * 4) +
                      (frow + 64 * j) * (AW * 4) + fq * 16) = uu;
        }
    };
    auto ldB = [&](int stage, int t) {
        unsigned b_s = smB + (unsigned)stage * (BSZW * 4u) + bSb;
        const unsigned* b_g = Bp + (size_t)(t * 16 + brow) * HD + n0 + bc * 4;
#pragma unroll
        for (int j = 0; j < 2; j++) {
            asm volatile("cp.async.cg.shared.global [%0], [%1], 16;"
                         :: "r"(b_s + (unsigned)(j * 256)), "l"(b_g + j * 64));
        }
        asm volatile("cp.async.commit_group;");
    };

    float acc[4][4][4];
#pragma unroll
    for (int a = 0; a < 4; a++)
#pragma unroll
        for (int b = 0; b < 4; b++)
#pragma unroll
            for (int c = 0; c < 4; c++) acc[a][b][c] = 0.f;

    const int lane = tid & 31, ly = lane >> 2, lx = lane & 3;
    const int wid = tid >> 5;
    const int wm = (wid & 1) * 64;
    const int wn = (tid >> 6) * 32;

    ldB(0, 0);
    ldgA(0);
    __syncthreads();  // s_sc/s_sh visible before first transform
    stsA(0, 0);
    ldgA(1);

#pragma unroll 1
    for (int t = 0; t < 32; t++) {
        if (t < 31) {
            ldB((t + 1) & 1, t + 1);
            asm volatile("cp.async.wait_group 1;");
        } else {
            asm volatile("cp.async.wait_group 0;");
        }
        __syncthreads();  // B[t] + stsA(t) visible; compute(t-1) done
        if (t < 31) {
            stsA((t + 1) & 1, t + 1);
            if (t < 30) ldgA(t + 2);
        }
        gemm_tile_h((const unsigned*)sm + (t & 1) * ASZW,
                    (const unsigned*)sm + 2 * ASZW + (t & 1) * BSZW, acc, wm, wn,
                    ly, lx);
        __syncthreads();
    }
    gemm_epilogue(acc, bias, C, ps, pq, sred, qred, m0, n0, wm, wn, wid, lane,
                  ly, lx, tid);
}

// ---------------- final: thetas = relu(bn(h3)) @ W4 + b4; kinematics ------
__device__ __forceinline__ void dh_mat(float M[3][4], float th, float r, float ca,
                                       float sa) {
    float ct = cosf(th), st = sinf(th);
    M[0][0] = ct;  M[0][1] = -st * ca; M[0][2] = st * sa;  M[0][3] = r * ct;
    M[1][0] = st;  M[1][1] = ct * ca;  M[1][2] = -ct * sa; M[1][3] = r * st;
    M[2][0] = 0.f; M[2][1] = sa;       M[2][2] = ca;       M[2][3] = 0.f;
}

__device__ __forceinline__ void matmul34(const float A[3][4], const float Bm[3][4],
                                         float C[3][4]) {
#pragma unroll
    for (int i = 0; i < 3; i++) {
#pragma unroll
        for (int j = 0; j < 4; j++) {
            float v = A[i][0] * Bm[0][j] + A[i][1] * Bm[1][j] + A[i][2] * Bm[2][j];
            if (j == 3) v += A[i][3];
            C[i][j] = v;
        }
    }
}

__global__ void k_final(const float* __restrict__ h3, const float* __restrict__ scale,
                        const float* __restrict__ shift, const float* __restrict__ W4,
                        const float* __restrict__ b4, float* __restrict__ out) {
    __shared__ float w4s[3072];
    __shared__ float b4s[3];
    const int tid = threadIdx.x;
    for (int i = tid; i < 3072; i += 256) w4s[i] = W4[i];
    if (tid < 3) b4s[tid] = b4[tid];
    __syncthreads();

    const int lane = tid & 31;
    const size_t row = (size_t)blockIdx.x * 8 + (tid >> 5);
    const float* hr = h3 + row * HD;
    float t0 = 0.f, t1 = 0.f, t2 = 0.f;
    for (int k = lane; k < HD; k += 32) {
        float a = fmaxf(fmaf(hr[k], scale[k], shift[k]), 0.f);
        t0 = fmaf(a, w4s[3 * k + 0], t0);
        t1 = fmaf(a, w4s[3 * k + 1], t1);
        t2 = fmaf(a, w4s[3 * k + 2], t2);
    }
#pragma unroll
    for (int o = 16; o > 0; o >>= 1) {
        t0 += __shfl_xor_sync(0xffffffffu, t0, o);
        t1 += __shfl_xor_sync(0xffffffffu, t1, o);
        t2 += __shfl_xor_sync(0xffffffffu, t2, o);
    }
    if (lane == 0) {
        const float th0 = t0 + b4s[0];
        const float th1 = t1 + b4s[1];
        const float th2 = t2 + b4s[2];
        out[row * 3 + 0] = th0;
        out[row * 3 + 1] = th1;
        out[row * 3 + 2] = th2;

        const float PI2 = 1.57079632679489661923f;
        float M[3][4], Nn[3][4], P[3][4];
        dh_mat(M, th0, 0.f, cosf(PI2), sinf(PI2));
        dh_mat(Nn, th1, 0.12f, 1.f, 0.f);
        matmul34(M, Nn, P);
        dh_mat(Nn, th2, 0.115f, 1.f, 0.f);
        matmul34(P, Nn, M);
        float* op = out + (size_t)BB * 3 + row * 3;
        op[0] = M[0][3];
        op[1] = M[1][3];
        op[2] = M[2][3];
    }
}

// ---------------- launch ---------------------------------------------------
extern "C" void kernel_launch(void* const* d_in, const int* in_sizes, int n_in,
                              void* d_out, int out_size) {
    const float* x   = (const float*)d_in[0];
    const float* W1  = (const float*)d_in[1];
    const float* b1  = (const float*)d_in[2];
    const float* g1  = (const float*)d_in[3];
    const float* bt1 = (const float*)d_in[4];
    const float* W2  = (const float*)d_in[5];
    const float* b2  = (const float*)d_in[6];
    const float* g2  = (const float*)d_in[7];
    const float* bt2 = (const float*)d_in[8];
    const float* W3  = (const float*)d_in[9];
    const float* b3  = (const float*)d_in[10];
    const float* g3  = (const float*)d_in[11];
    const float* bt3 = (const float*)d_in[12];
    const float* W4  = (const float*)d_in[13];
    const float* b4  = (const float*)d_in[14];
    float* out = (float*)d_out;

    void *p_h2, *p_h3, *p_acth, *p_w2p, *p_w3p, *p_ps, *p_pq, *p_sc, *p_sh;
    cudaGetSymbolAddress(&p_h2, g_h2);
    cudaGetSymbolAddress(&p_h3, g_h3);
    cudaGetSymbolAddress(&p_acth, g_acth);
    cudaGetSymbolAddress(&p_w2p, g_w2p);
    cudaGetSymbolAddress(&p_w3p, g_w3p);
    cudaGetSymbolAddress(&p_ps, g_ps);
    cudaGetSymbolAddress(&p_pq, g_pq);
    cudaGetSymbolAddress(&p_sc, g_scale);
    cudaGetSymbolAddress(&p_sh, g_shift);
    float* h2 = (float*)p_h2;
    float* h3 = (float*)p_h3;
    unsigned* acth = (unsigned*)p_acth;
    unsigned* w2p = (unsigned*)p_w2p;
    unsigned* w3p = (unsigned*)p_w3p;
    float* ps = (float*)p_ps;
    float* pq = (float*)p_pq;
    float* sc = (float*)p_sc;
    float* sh = (float*)p_sh;

    cudaFuncSetAttribute(k_gemm, cudaFuncAttributeMaxDynamicSharedMemorySize,
                         GEMM_SMEM_H);
    cudaFuncSetAttribute(k_gemm_f, cudaFuncAttributeMaxDynamicSharedMemorySize,
                         GEMMF_SMEM_H);

    const dim3 gemmGrid(8, BB / 128);  // n fastest -> A L2 reuse

    // pack weights to half2 [k/2][n] once per call
    k_cvtwp<<<dim3(HD / 256, HD / 2), 256>>>(W2, w2p);
    k_cvtwp<<<dim3(HD / 256, HD / 2), 256>>>(W3, w3p);

    // layer 1: stats only (no h1 materialization), then recompute+act (fp16)
    k_layer1_stats<<<BB / 256, 256>>>(x, W1, b1, ps, pq);
    k_reduce2<<<HD, 256>>>(ps, pq, g1, bt1, sc, sh, BB / 256);
    k_act1<<<BB / 256, 256>>>(x, W1, b1, sc, sh, acth);

    // layer 2: fp16 GEMM (A = fp16 act), fused column stats
    k_gemm<<<gemmGrid, 256, GEMM_SMEM_H>>>(acth, w2p, b2, h2, ps, pq);
    k_reduce2<<<HD, 256>>>(ps, pq, g2, bt2, sc, sh, BB / 128);

    // layer 3: fused fp16 GEMM reads raw fp32 h2, BN+ReLU+fp16 at smem-store
    k_gemm_f<<<gemmGrid, 256, GEMMF_SMEM_H>>>(h2, w3p, b3, sc, sh, h3, ps, pq);
    k_reduce2<<<HD, 256>>>(ps, pq, g3, bt3, sc, sh, BB / 128);

    // final layer (fp32, BN fused) + forward kinematics
    k_final<<<BB / 8, 256>>>(h3, sc, sh, W4, b4, out);
}

// round 16
// speedup vs baseline: 1.7806x; 1.0801x over previous
#include <cuda_runtime.h>
#include <cuda_fp16.h>
#include <math.h>
#include <stdint.h>

#define BB 131072
#define HD 1024

// ---------------- scratch (device globals; no allocation) ----------------
__device__ unsigned g_h2h[(size_t)BB * HD / 2];   // 256MB: h2 fp16 (pre-BN)
__device__ unsigned g_h3h[(size_t)BB * HD / 2];   // 256MB: h3 fp16 (pre-BN)
__device__ unsigned g_acth[(size_t)BB * HD / 2];  // 256MB: layer1 act fp16
__device__ unsigned g_w2p[(HD / 2) * HD];         // W2 packed half2 [k/2][n]
__device__ unsigned g_w3p[(HD / 2) * HD];         // W3 packed half2 [k/2][n]
__device__ float g_ps[1024 * HD];
__device__ float g_pq[1024 * HD];
__device__ float g_scale[HD];
__device__ float g_shift[HD];

// ---------------- helpers ----------------
__device__ __forceinline__ unsigned pack_h2(float a, float b) {
    unsigned u;
    asm("{\n\t.reg .f16 lo, hi;\n\t"
        "cvt.rn.f16.f32 lo, %1;\n\t"
        "cvt.rn.f16.f32 hi, %2;\n\t"
        "mov.b32 %0, {lo, hi};\n\t}"
        : "=r"(u) : "f"(a), "f"(b));
    return u;
}
__device__ __forceinline__ float2 unpack_h2(unsigned u) {
    return __half22float2(*reinterpret_cast<const __half2*>(&u));
}

// ---------------- layer1 stats: partial sums of x@W1+b1 (no h store) ------
__global__ void k_layer1_stats(const float* __restrict__ x,
                               const float* __restrict__ W1,
                               const float* __restrict__ b1,
                               float* __restrict__ ps, float* __restrict__ pq) {
    __shared__ float xs[256 * 3];
    const int blk = blockIdx.x;
    const int tid = threadIdx.x;
    const int row0 = blk * 256;
    for (int i = tid; i < 768; i += 256) xs[i] = x[(size_t)row0 * 3 + i];
    __syncthreads();

    const int c = tid * 4;
    float w0[4], w1[4], w2[4], bb[4];
#pragma unroll
    for (int e = 0; e < 4; e++) {
        w0[e] = W1[c + e];
        w1[e] = W1[HD + c + e];
        w2[e] = W1[2 * HD + c + e];
        bb[e] = b1[c + e];
    }
    float s[4] = {0.f, 0.f, 0.f, 0.f}, q[4] = {0.f, 0.f, 0.f, 0.f};
    for (int r = 0; r < 256; r++) {
        float x0 = xs[3 * r], x1 = xs[3 * r + 1], x2 = xs[3 * r + 2];
#pragma unroll
        for (int e = 0; e < 4; e++) {
            float t = fmaf(x0, w0[e], bb[e]);
            t = fmaf(x1, w1[e], t);
            t = fmaf(x2, w2[e], t);
            s[e] += t;
            q[e] = fmaf(t, t, q[e]);
        }
    }
#pragma unroll
    for (int e = 0; e < 4; e++) {
        ps[(size_t)blk * HD + c + e] = s[e];
        pq[(size_t)blk * HD + c + e] = q[e];
    }
}

// ---------------- layer1 act: recompute h1, BN+ReLU -> fp16 act -----------
__global__ void k_act1(const float* __restrict__ x, const float* __restrict__ W1,
                       const float* __restrict__ b1, const float* __restrict__ scale,
                       const float* __restrict__ shift, unsigned* __restrict__ acth) {
    __shared__ float xs[256 * 3];
    const int blk = blockIdx.x;
    const int tid = threadIdx.x;
    const int row0 = blk * 256;
    for (int i = tid; i < 768; i += 256) xs[i] = x[(size_t)row0 * 3 + i];
    __syncthreads();

    const int c = tid * 4;
    float w0[4], w1[4], w2[4], bb[4], sc[4], sh[4];
#pragma unroll
    for (int e = 0; e < 4; e++) {
        w0[e] = W1[c + e];
        w1[e] = W1[HD + c + e];
        w2[e] = W1[2 * HD + c + e];
        bb[e] = b1[c + e];
        sc[e] = scale[c + e];
        sh[e] = shift[c + e];
    }
    for (int r = 0; r < 256; r++) {
        float x0 = xs[3 * r], x1 = xs[3 * r + 1], x2 = xs[3 * r + 2];
        float v[4];
#pragma unroll
        for (int e = 0; e < 4; e++) {
            float t = fmaf(x0, w0[e], bb[e]);
            t = fmaf(x1, w1[e], t);
            t = fmaf(x2, w2[e], t);
            v[e] = fmaxf(fmaf(t, sc[e], sh[e]), 0.f);
        }
        ((uint2*)acth)[(size_t)(row0 + r) * 256 + tid] =
            make_uint2(pack_h2(v[0], v[1]), pack_h2(v[2], v[3]));
    }
}

// ---------------- reduce partials -> per-column scale/shift (1 blk/col) ---
__global__ void k_reduce2(const float* __restrict__ ps, const float* __restrict__ pq,
                          const float* __restrict__ g, const float* __restrict__ bt,
                          float* __restrict__ scale, float* __restrict__ shift,
                          int parts) {
    const int c = blockIdx.x;
    const int tid = threadIdx.x;
    float s = 0.f, q = 0.f;
    for (int p = tid; p < parts; p += 256) {
        s += ps[(size_t)p * HD + c];
        q += pq[(size_t)p * HD + c];
    }
    __shared__ float ss[8], qq[8];
#pragma unroll
    for (int o = 16; o; o >>= 1) {
        s += __shfl_xor_sync(0xffffffffu, s, o);
        q += __shfl_xor_sync(0xffffffffu, q, o);
    }
    if ((tid & 31) == 0) { ss[tid >> 5] = s; qq[tid >> 5] = q; }
    __syncthreads();
    if (tid == 0) {
        float S = 0.f, Q = 0.f;
#pragma unroll
        for (int w = 0; w < 8; w++) { S += ss[w]; Q += qq[w]; }
        const float invB = 1.0f / (float)BB;
        float mu = S * invB;
        float var = fmaxf(Q * invB - mu * mu, 0.f);
        float sc = g[c] * rsqrtf(var + 1e-5f);
        scale[c] = sc;
        shift[c] = bt[c] - mu * sc;
    }
}

// ---------------- weight: fp32 -> packed half2 [k/2][n] -------------------
__global__ void k_cvtwp(const float* __restrict__ w, unsigned* __restrict__ o) {
    const int n = blockIdx.x * 256 + threadIdx.x;
    const int k2 = blockIdx.y;
    o[(size_t)k2 * HD + n] =
        pack_h2(w[(size_t)(2 * k2) * HD + n], w[(size_t)(2 * k2 + 1) * HD + n]);
}

// ---------------- fp16 GEMM config ----------------------------------------
// CTA tile 128x128x32, 8 warps (2x4), m16n8k16 f16 mma.sync (fp32 accum),
// cp.async 2-stage. A smem: 128 rows x 16 half2, stride 20 words; fragments
// via ldmatrix.x4 (rows r*20 mod 32 span disjoint 16B groups -> no conflicts).
// B smem: 16 k-pair rows x 128 half2, stride 136 (8*lx+ly distinct).
#define AW 20
#define BW 136
#define ASZW (128 * AW)  // 2560 words
#define BSZW (16 * BW)   // 2176 words
#define GEMM_SMEM_H (2 * (ASZW + BSZW) * 4)       // 37888
#define GEMMF_SMEM_H (GEMM_SMEM_H + 2 * HD * 4)   // 46080

// Shared epilogue: store C(fp16) = acc + bias, fused fp32 column stats.
__device__ __forceinline__ void gemm_epilogue(
    float acc[4][4][4], const float* __restrict__ bias, unsigned* __restrict__ C,
    float* __restrict__ ps, float* __restrict__ pq, float sred[8][32],
    float qred[8][32], int m0, int n0, int wm, int wn, int wid, int lane, int ly,
    int lx, int tid) {
    float sc_[4][2] = {{0.f, 0.f}, {0.f, 0.f}, {0.f, 0.f}, {0.f, 0.f}};
    float qc_[4][2] = {{0.f, 0.f}, {0.f, 0.f}, {0.f, 0.f}, {0.f, 0.f}};
#pragma unroll
    for (int mi = 0; mi < 4; mi++) {
        const int r0 = m0 + wm + mi * 16 + ly;
#pragma unroll
        for (int ni = 0; ni < 4; ni++) {
            const int c = n0 + wn + ni * 8 + 2 * lx;
            const float bc0 = bias[c], bc1 = bias[c + 1];
            float2 v0 = make_float2(acc[mi][ni][0] + bc0, acc[mi][ni][1] + bc1);
            float2 v1 = make_float2(acc[mi][ni][2] + bc0, acc[mi][ni][3] + bc1);
            C[(size_t)r0 * (HD / 2) + c / 2] = pack_h2(v0.x, v0.y);
            C[(size_t)(r0 + 8) * (HD / 2) + c / 2] = pack_h2(v1.x, v1.y);
            sc_[ni][0] += v0.x + v1.x;
            sc_[ni][1] += v0.y + v1.y;
            qc_[ni][0] = fmaf(v0.x, v0.x, fmaf(v1.x, v1.x, qc_[ni][0]));
            qc_[ni][1] = fmaf(v0.y, v0.y, fmaf(v1.y, v1.y, qc_[ni][1]));
        }
    }
#pragma unroll
    for (int ni = 0; ni < 4; ni++) {
#pragma unroll
        for (int j = 0; j < 2; j++) {
            float s = sc_[ni][j], q = qc_[ni][j];
#pragma unroll
            for (int o = 4; o <= 16; o <<= 1) {
                s += __shfl_xor_sync(0xffffffffu, s, o);
                q += __shfl_xor_sync(0xffffffffu, q, o);
            }
            if (lane < 4) {
                sred[wid][ni * 8 + 2 * lx + j] = s;
                qred[wid][ni * 8 + 2 * lx + j] = q;
            }
        }
    }
    __syncthreads();
    if (tid < 128) {
        const int col = tid;
        const int gpair = (col >> 5) * 2;
        const int cc = col & 31;
        ps[(size_t)blockIdx.y * HD + n0 + col] = sred[gpair][cc] + sred[gpair + 1][cc];
        pq[(size_t)blockIdx.y * HD + n0 + col] = qred[gpair][cc] + qred[gpair + 1][cc];
    }
}

// One K=32 tile: A via ldmatrix.x4, B via scalar LDS, 32 m16n8k16 MMAs/warp.
__device__ __forceinline__ void gemm_tile_h(unsigned aT, const unsigned* Bs,
                                            float acc[4][4][4], int wn, int ly,
                                            int lx) {
#pragma unroll
    for (int kk2 = 0; kk2 < 16; kk2 += 8) {
        unsigned af[4][4], bf[4][2];
#pragma unroll
        for (int mi = 0; mi < 4; mi++) {
            const unsigned ad = aT + (unsigned)((mi * 16 * AW + kk2) * 4);
            asm volatile(
                "ldmatrix.sync.aligned.m8n8.x4.shared.b16 {%0,%1,%2,%3}, [%4];"
                : "=r"(af[mi][0]), "=r"(af[mi][1]), "=r"(af[mi][2]),
                  "=r"(af[mi][3])
                : "r"(ad));
        }
#pragma unroll
        for (int ni = 0; ni < 4; ni++) {
            const unsigned* p = Bs + (kk2 + lx) * BW + wn + ni * 8 + ly;
            bf[ni][0] = p[0];
            bf[ni][1] = p[4 * BW];
        }
#pragma unroll
        for (int mi = 0; mi < 4; mi++)
#pragma unroll
            for (int ni = 0; ni < 4; ni++) {
                asm volatile(
                    "mma.sync.aligned.m16n8k16.row.col.f32.f16.f16.f32 "
                    "{%0,%1,%2,%3}, {%4,%5,%6,%7}, {%8,%9}, {%0,%1,%2,%3};"
                    : "+f"(acc[mi][ni][0]), "+f"(acc[mi][ni][1]),
                      "+f"(acc[mi][ni][2]), "+f"(acc[mi][ni][3])
                    : "r"(af[mi][0]), "r"(af[mi][1]), "r"(af[mi][2]), "r"(af[mi][3]),
                      "r"(bf[ni][0]), "r"(bf[ni][1]));
            }
    }
}

// ---------------- plain fp16 GEMM: C = Ah@W + bias (A = fp16) -------------
__global__ void __launch_bounds__(256, 2)
k_gemm(const unsigned* __restrict__ Ah, const unsigned* __restrict__ Bp,
       const float* __restrict__ bias, unsigned* __restrict__ C,
       float* __restrict__ ps, float* __restrict__ pq) {
    extern __shared__ float sm[];
    __shared__ float sred[8][32], qred[8][32];
    const int tid = threadIdx.x;
    const int m0 = blockIdx.y * 128;
    const int n0 = blockIdx.x * 128;

    const unsigned smA = (unsigned)__cvta_generic_to_shared(sm);
    const unsigned smB = smA + 2u * ASZW * 4u;

    const int arow = tid >> 2, aq = tid & 3;
    const int brow = tid >> 4, bc = tid & 15;

    const unsigned* Agw = Ah + (size_t)(m0 + arow) * (HD / 2) + aq * 4;
    const unsigned aSb = (unsigned)(arow * AW * 4 + aq * 16);
    const unsigned bSb = (unsigned)(brow * BW * 4 + bc * 16);

    auto load_tile = [&](int stage, int t) {
        unsigned a_s = smA + (unsigned)stage * (ASZW * 4u) + aSb;
        const unsigned* a_g = Agw + t * 16;
#pragma unroll
        for (int j = 0; j < 2; j++) {
            asm volatile("cp.async.cg.shared.global [%0], [%1], 16;"
                         :: "r"(a_s + (unsigned)(j * 64 * AW * 4)),
                            "l"(a_g + (size_t)64 * (HD / 2) * j));
        }
        unsigned b_s = smB + (unsigned)stage * (BSZW * 4u) + bSb;
        const unsigned* b_g = Bp + (size_t)(t * 16 + brow) * HD + n0 + bc * 4;
#pragma unroll
        for (int j = 0; j < 2; j++) {
            asm volatile("cp.async.cg.shared.global [%0], [%1], 16;"
                         :: "r"(b_s + (unsigned)(j * 256)), "l"(b_g + j * 64));
        }
        asm volatile("cp.async.commit_group;");
    };

    float acc[4][4][4];
#pragma unroll
    for (int a = 0; a < 4; a++)
#pragma unroll
        for (int b = 0; b < 4; b++)
#pragma unroll
            for (int c = 0; c < 4; c++) acc[a][b][c] = 0.f;

    const int lane = tid & 31, ly = lane >> 2, lx = lane & 3;
    const int wid = tid >> 5;
    const int wm = (wid & 1) * 64;
    const int wn = (tid >> 6) * 32;

    // ldmatrix per-lane base: lanes 0-15 -> rows, lanes 16-31 -> +k8 (16B)
    const unsigned aLane =
        smA + (unsigned)(((wm + (lane & 15)) * AW) * 4 + (lane >> 4) * 16);

    load_tile(0, 0);
#pragma unroll 1
    for (int t = 0; t < 32; t++) {
        if (t < 31) {
            load_tile((t + 1) & 1, t + 1);
            asm volatile("cp.async.wait_group 1;");
        } else {
            asm volatile("cp.async.wait_group 0;");
        }
        __syncthreads();
        gemm_tile_h(aLane + (unsigned)((t & 1) * ASZW * 4),
                    (const unsigned*)sm + 2 * ASZW + (t & 1) * BSZW, acc, wn, ly,
                    lx);
        __syncthreads();
    }
    gemm_epilogue(acc, bias, C, ps, pq, sred, qred, m0, n0, wm, wn, wid, lane,
                  ly, lx, tid);
}

// ---------------- fused fp16 GEMM: C = act(A)@W + bias --------------------
// A holds raw fp16 pre-BN h2; LDG.128(half2) -> BN+ReLU (fp32) -> fp16 STS.
__global__ void __launch_bounds__(256, 2)
k_gemm_f(const unsigned* __restrict__ Ah, const unsigned* __restrict__ Bp,
         const float* __restrict__ bias, const float* __restrict__ scA,
         const float* __restrict__ shA, unsigned* __restrict__ C,
         float* __restrict__ ps, float* __restrict__ pq) {
    extern __shared__ float sm[];
    __shared__ float sred[8][32], qred[8][32];
    const int tid = threadIdx.x;
    const int m0 = blockIdx.y * 128;
    const int n0 = blockIdx.x * 128;

    float* s_sc = sm + 2 * (ASZW + BSZW);
    float* s_sh = s_sc + HD;

    const unsigned smA = (unsigned)__cvta_generic_to_shared(sm);
    const unsigned smB = smA + 2u * ASZW * 4u;

    const int frow = tid >> 2, fq = tid & 3;  // rows frow, frow+64; k words fq*4..+3
    const int brow = tid >> 4, bc = tid & 15;
    const unsigned bSb = (unsigned)(brow * BW * 4 + bc * 16);

    for (int i = tid; i < HD; i += 256) {
        s_sc[i] = scA[i];
        s_sh[i] = shA[i];
    }

    uint4 av[2];
    auto ldgA = [&](int t) {
#pragma unroll
        for (int j = 0; j < 2; j++) {
            av[j] = *(const uint4*)(Ah + (size_t)(m0 + frow + 64 * j) * (HD / 2) +
                                    t * 16 + fq * 4);
        }
    };
    auto stsA = [&](int stage, int t) {
        const float4 sc0 = *(const float4*)(s_sc + t * 32 + fq * 8);
        const float4 sc1 = *(const float4*)(s_sc + t * 32 + fq * 8 + 4);
        const float4 sh0 = *(const float4*)(s_sh + t * 32 + fq * 8);
        const float4 sh1 = *(const float4*)(s_sh + t * 32 + fq * 8 + 4);
#pragma unroll
        for (int j = 0; j < 2; j++) {
            float2 f0 = unpack_h2(av[j].x);
            float2 f1 = unpack_h2(av[j].y);
            float2 f2 = unpack_h2(av[j].z);
            float2 f3 = unpack_h2(av[j].w);
            uint4 uu;
            uu.x = pack_h2(fmaxf(fmaf(f0.x, sc0.x, sh0.x), 0.f),
                           fmaxf(fmaf(f0.y, sc0.y, sh0.y), 0.f));
            uu.y = pack_h2(fmaxf(fmaf(f1.x, sc0.z, sh0.z), 0.f),
                           fmaxf(fmaf(f1.y, sc0.w, sh0.w), 0.f));
            uu.z = pack_h2(fmaxf(fmaf(f2.x, sc1.x, sh1.x), 0.f),
                           fmaxf(fmaf(f2.y, sc1.y, sh1.y), 0.f));
            uu.w = pack_h2(fmaxf(fmaf(f3.x, sc1.z, sh1.z), 0.f),
                           fmaxf(fmaf(f3.y, sc1.w, sh1.w), 0.f));
            *(uint4*)((char*)sm + (size_t)stage * (ASZW * 4) +
                      (frow + 64 * j) * (AW * 4) + fq * 16) = uu;
        }
    };
    auto ldB = [&](int stage, int t) {
        unsigned b_s = smB + (unsigned)stage * (BSZW * 4u) + bSb;
        const unsigned* b_g = Bp + (size_t)(t * 16 + brow) * HD + n0 + bc * 4;
#pragma unroll
        for (int j = 0; j < 2; j++) {
            asm volatile("cp.async.cg.shared.global [%0], [%1], 16;"
                         :: "r"(b_s + (unsigned)(j * 256)), "l"(b_g + j * 64));
        }
        asm volatile("cp.async.commit_group;");
    };

    float acc[4][4][4];
#pragma unroll
    for (int a = 0; a < 4; a++)
#pragma unroll
        for (int b = 0; b < 4; b++)
#pragma unroll
            for (int c = 0; c < 4; c++) acc[a][b][c] = 0.f;

    const int lane = tid & 31, ly = lane >> 2, lx = lane & 3;
    const int wid = tid >> 5;
    const int wm = (wid & 1) * 64;
    const int wn = (tid >> 6) * 32;
    const unsigned aLane =
        smA + (unsigned)(((wm + (lane & 15)) * AW) * 4 + (lane >> 4) * 16);

    ldB(0, 0);
    ldgA(0);
    __syncthreads();  // s_sc/s_sh visible before first transform
    stsA(0, 0);
    ldgA(1);

#pragma unroll 1
    for (int t = 0; t < 32; t++) {
        if (t < 31) {
            ldB((t + 1) & 1, t + 1);
            asm volatile("cp.async.wait_group 1;");
        } else {
            asm volatile("cp.async.wait_group 0;");
        }
        __syncthreads();  // B[t] + stsA(t) visible; compute(t-1) done
        if (t < 31) {
            stsA((t + 1) & 1, t + 1);
            if (t < 30) ldgA(t + 2);
        }
        gemm_tile_h(aLane + (unsigned)((t & 1) * ASZW * 4),
                    (const unsigned*)sm + 2 * ASZW + (t & 1) * BSZW, acc, wn, ly,
                    lx);
        __syncthreads();
    }
    gemm_epilogue(acc, bias, C, ps, pq, sred, qred, m0, n0, wm, wn, wid, lane,
                  ly, lx, tid);
}

// ---------------- final: thetas = relu(bn(h3)) @ W4 + b4; kinematics ------
__device__ __forceinline__ void dh_mat(float M[3][4], float th, float r, float ca,
                                       float sa) {
    float ct = cosf(th), st = sinf(th);
    M[0][0] = ct;  M[0][1] = -st * ca; M[0][2] = st * sa;  M[0][3] = r * ct;
    M[1][0] = st;  M[1][1] = ct * ca;  M[1][2] = -ct * sa; M[1][3] = r * st;
    M[2][0] = 0.f; M[2][1] = sa;       M[2][2] = ca;       M[2][3] = 0.f;
}

__device__ __forceinline__ void matmul34(const float A[3][4], const float Bm[3][4],
                                         float C[3][4]) {
#pragma unroll
    for (int i = 0; i < 3; i++) {
#pragma unroll
        for (int j = 0; j < 4; j++) {
            float v = A[i][0] * Bm[0][j] + A[i][1] * Bm[1][j] + A[i][2] * Bm[2][j];
            if (j == 3) v += A[i][3];
            C[i][j] = v;
        }
    }
}

__global__ void k_final(const unsigned* __restrict__ h3h,
                        const float* __restrict__ scale,
                        const float* __restrict__ shift, const float* __restrict__ W4,
                        const float* __restrict__ b4, float* __restrict__ out) {
    __shared__ float w4s[3072];
    __shared__ float b4s[3];
    const int tid = threadIdx.x;
    for (int i = tid; i < 3072; i += 256) w4s[i] = W4[i];
    if (tid < 3) b4s[tid] = b4[tid];
    __syncthreads();

    const int lane = tid & 31;
    const size_t row = (size_t)blockIdx.x * 8 + (tid >> 5);
    const unsigned* hr = h3h + row * (HD / 2);
    float t0 = 0.f, t1 = 0.f, t2 = 0.f;
    for (int k2 = lane; k2 < HD / 2; k2 += 32) {
        float2 f = unpack_h2(hr[k2]);
        const int k = 2 * k2;
        float a0 = fmaxf(fmaf(f.x, scale[k], shift[k]), 0.f);
        float a1 = fmaxf(fmaf(f.y, scale[k + 1], shift[k + 1]), 0.f);
        t0 = fmaf(a0, w4s[3 * k + 0], fmaf(a1, w4s[3 * k + 3], t0));
        t1 = fmaf(a0, w4s[3 * k + 1], fmaf(a1, w4s[3 * k + 4], t1));
        t2 = fmaf(a0, w4s[3 * k + 2], fmaf(a1, w4s[3 * k + 5], t2));
    }
#pragma unroll
    for (int o = 16; o > 0; o >>= 1) {
        t0 += __shfl_xor_sync(0xffffffffu, t0, o);
        t1 += __shfl_xor_sync(0xffffffffu, t1, o);
        t2 += __shfl_xor_sync(0xffffffffu, t2, o);
    }
    if (lane == 0) {
        const float th0 = t0 + b4s[0];
        const float th1 = t1 + b4s[1];
        const float th2 = t2 + b4s[2];
        out[row * 3 + 0] = th0;
        out[row * 3 + 1] = th1;
        out[row * 3 + 2] = th2;

        const float PI2 = 1.57079632679489661923f;
        float M[3][4], Nn[3][4], P[3][4];
        dh_mat(M, th0, 0.f, cosf(PI2), sinf(PI2));
        dh_mat(Nn, th1, 0.12f, 1.f, 0.f);
        matmul34(M, Nn, P);
        dh_mat(Nn, th2, 0.115f, 1.f, 0.f);
        matmul34(P, Nn, M);
        float* op = out + (size_t)BB * 3 + row * 3;
        op[0] = M[0][3];
        op[1] = M[1][3];
        op[2] = M[2][3];
    }
}

// ---------------- launch ---------------------------------------------------
extern "C" void kernel_launch(void* const* d_in, const int* in_sizes, int n_in,
                              void* d_out, int out_size) {
    const float* x   = (const float*)d_in[0];
    const float* W1  = (const float*)d_in[1];
    const float* b1  = (const float*)d_in[2];
    const float* g1  = (const float*)d_in[3];
    const float* bt1 = (const float*)d_in[4];
    const float* W2  = (const float*)d_in[5];
    const float* b2  = (const float*)d_in[6];
    const float* g2  = (const float*)d_in[7];
    const float* bt2 = (const float*)d_in[8];
    const float* W3  = (const float*)d_in[9];
    const float* b3  = (const float*)d_in[10];
    const float* g3  = (const float*)d_in[11];
    const float* bt3 = (const float*)d_in[12];
    const float* W4  = (const float*)d_in[13];
    const float* b4  = (const float*)d_in[14];
    float* out = (float*)d_out;

    void *p_h2h, *p_h3h, *p_acth, *p_w2p, *p_w3p, *p_ps, *p_pq, *p_sc, *p_sh;
    cudaGetSymbolAddress(&p_h2h, g_h2h);
    cudaGetSymbolAddress(&p_h3h, g_h3h);
    cudaGetSymbolAddress(&p_acth, g_acth);
    cudaGetSymbolAddress(&p_w2p, g_w2p);
    cudaGetSymbolAddress(&p_w3p, g_w3p);
    cudaGetSymbolAddress(&p_ps, g_ps);
    cudaGetSymbolAddress(&p_pq, g_pq);
    cudaGetSymbolAddress(&p_sc, g_scale);
    cudaGetSymbolAddress(&p_sh, g_shift);
    unsigned* h2h = (unsigned*)p_h2h;
    unsigned* h3h = (unsigned*)p_h3h;
    unsigned* acth = (unsigned*)p_acth;
    unsigned* w2p = (unsigned*)p_w2p;
    unsigned* w3p = (unsigned*)p_w3p;
    float* ps = (float*)p_ps;
    float* pq = (float*)p_pq;
    float* sc = (float*)p_sc;
    float* sh = (float*)p_sh;

    cudaFuncSetAttribute(k_gemm, cudaFuncAttributeMaxDynamicSharedMemorySize,
                         GEMM_SMEM_H);
    cudaFuncSetAttribute(k_gemm_f, cudaFuncAttributeMaxDynamicSharedMemorySize,
                         GEMMF_SMEM_H);

    const dim3 gemmGrid(8, BB / 128);  // n fastest -> A L2 reuse

    // pack weights to half2 [k/2][n] once per call
    k_cvtwp<<<dim3(HD / 256, HD / 2), 256>>>(W2, w2p);
    k_cvtwp<<<dim3(HD / 256, HD / 2), 256>>>(W3, w3p);

    // layer 1: stats only (no h1 materialization), then recompute+act (fp16)
    k_layer1_stats<<<BB / 256, 256>>>(x, W1, b1, ps, pq);
    k_reduce2<<<HD, 256>>>(ps, pq, g1, bt1, sc, sh, BB / 256);
    k_act1<<<BB / 256, 256>>>(x, W1, b1, sc, sh, acth);

    // layer 2: fp16 GEMM (A = fp16 act), fp16 h2 out, fused column stats
    k_gemm<<<gemmGrid, 256, GEMM_SMEM_H>>>(acth, w2p, b2, h2h, ps, pq);
    k_reduce2<<<HD, 256>>>(ps, pq, g2, bt2, sc, sh, BB / 128);

    // layer 3: fused fp16 GEMM reads fp16 h2, BN+ReLU at smem-store, fp16 h3
    k_gemm_f<<<gemmGrid, 256, GEMMF_SMEM_H>>>(h2h, w3p, b3, sc, sh, h3h, ps, pq);
    k_reduce2<<<HD, 256>>>(ps, pq, g3, bt3, sc, sh, BB / 128);

    // final layer (fp32 accumulate, BN fused) + forward kinematics
    k_final<<<BB / 8, 256>>>(h3h, sc, sh, W4, b4, out);
}